// round 2
// baseline (speedup 1.0000x reference)
#include <cuda_runtime.h>
#include <cuda_bf16.h>
#include <mma.h>
#include <math.h>

using namespace nvcuda;

#define BB  2
#define SS  2048
#define HH  1024
#define NH  16
#define HD  64
#define MROWS (BB*SS)      // 4096

// ---------------- scratch (no allocations allowed) ----------------
__device__ float g_Q[(size_t)BB*SS*HH];
__device__ float g_K[(size_t)BB*SS*HH];
__device__ float g_V[(size_t)BB*SS*HH];
__device__ float g_CTX[(size_t)BB*SS*HH];

// =================================================================
// GEMM: C[M,N] = A[M,K] @ W[K,N], tf32 wmma, 128x128 block tile.
// permuted=1: write C to [B, NH, S, HD] layout (for Q/K/V).
// =================================================================
__global__ __launch_bounds__(256) void gemm128_tf32(
    const float* __restrict__ A, const float* __restrict__ Wm,
    float* __restrict__ C, int M, int N, int Kd, int permuted)
{
    __shared__ float sA[128][36];
    __shared__ float sB[32][132];

    const int tid = threadIdx.x;
    const int wid = tid >> 5;
    const int wm  = wid >> 2;   // 0..1  (64-row strip)
    const int wn  = wid & 3;    // 0..3  (32-col strip)
    const int m0  = blockIdx.y * 128;
    const int n0  = blockIdx.x * 128;

    wmma::fragment<wmma::accumulator, 16, 16, 8, float> acc[4][2];
    #pragma unroll
    for (int i = 0; i < 4; i++)
        #pragma unroll
        for (int j = 0; j < 2; j++)
            wmma::fill_fragment(acc[i][j], 0.0f);

    for (int kk = 0; kk < Kd; kk += 32) {
        // load A tile 128x32 (1024 float4, 4 per thread)
        #pragma unroll
        for (int i = 0; i < 4; i++) {
            int lin = tid + i * 256;
            int r = lin >> 3;
            int c4 = (lin & 7) << 2;
            float4 v = *reinterpret_cast<const float4*>(&A[(size_t)(m0 + r) * Kd + kk + c4]);
            sA[r][c4 + 0] = v.x; sA[r][c4 + 1] = v.y;
            sA[r][c4 + 2] = v.z; sA[r][c4 + 3] = v.w;
        }
        // load B tile 32x128
        #pragma unroll
        for (int i = 0; i < 4; i++) {
            int lin = tid + i * 256;
            int r = lin >> 5;
            int c4 = (lin & 31) << 2;
            float4 v = *reinterpret_cast<const float4*>(&Wm[(size_t)(kk + r) * N + n0 + c4]);
            sB[r][c4 + 0] = v.x; sB[r][c4 + 1] = v.y;
            sB[r][c4 + 2] = v.z; sB[r][c4 + 3] = v.w;
        }
        __syncthreads();

        #pragma unroll
        for (int ks = 0; ks < 4; ks++) {
            wmma::fragment<wmma::matrix_a, 16, 16, 8, wmma::precision::tf32, wmma::row_major> af[4];
            wmma::fragment<wmma::matrix_b, 16, 16, 8, wmma::precision::tf32, wmma::row_major> bf[2];
            #pragma unroll
            for (int i = 0; i < 4; i++) {
                wmma::load_matrix_sync(af[i], &sA[wm * 64 + i * 16][ks * 8], 36);
                #pragma unroll
                for (int t = 0; t < af[i].num_elements; t++)
                    af[i].x[t] = wmma::__float_to_tf32(af[i].x[t]);
            }
            #pragma unroll
            for (int j = 0; j < 2; j++) {
                wmma::load_matrix_sync(bf[j], &sB[ks * 8][wn * 32 + j * 16], 132);
                #pragma unroll
                for (int t = 0; t < bf[j].num_elements; t++)
                    bf[j].x[t] = wmma::__float_to_tf32(bf[j].x[t]);
            }
            #pragma unroll
            for (int i = 0; i < 4; i++)
                #pragma unroll
                for (int j = 0; j < 2; j++)
                    wmma::mma_sync(acc[i][j], af[i], bf[j], acc[i][j]);
        }
        __syncthreads();
    }

    // epilogue
    #pragma unroll
    for (int i = 0; i < 4; i++) {
        #pragma unroll
        for (int j = 0; j < 2; j++) {
            int r0 = m0 + wm * 64 + i * 16;
            int c0 = n0 + wn * 32 + j * 16;
            if (permuted) {
                int b  = r0 >> 11;          // / S
                int s  = r0 & (SS - 1);
                int h  = c0 >> 6;           // / HD
                int hd = c0 & (HD - 1);
                float* p = C + (((size_t)(b * NH + h) * SS + s) << 6) + hd;
                wmma::store_matrix_sync(p, acc[i][j], HD, wmma::mem_row_major);
            } else {
                wmma::store_matrix_sync(C + (size_t)r0 * N + c0, acc[i][j], N, wmma::mem_row_major);
            }
        }
    }
}

// =================================================================
// Flash attention: 64-query tile per CTA, 64-key tiles, online softmax.
// Q/K/V in [B, NH, S, HD] fp32. Writes context to [B, S, H].
// =================================================================
__global__ __launch_bounds__(256, 2) void attn_kernel(
    const float* __restrict__ Q, const float* __restrict__ Kg,
    const float* __restrict__ Vg, const int* __restrict__ maskg,
    float* __restrict__ CTX)
{
    extern __shared__ float smbuf[];
    float* sQ   = smbuf;                 // 64x68
    float* sK   = sQ + 64 * 68;          // 64x68 (also aliased as PV buffer)
    float* sV   = sK + 64 * 68;          // 64x68
    float* sS   = sV + 64 * 68;          // 64x68 (scores, then P)
    float* sO   = sS + 64 * 68;          // 64x68 accumulator
    float* rowm = sO + 64 * 68;          // 64
    float* rowl = rowm + 64;             // 64
    float* rowc = rowl + 64;             // 64
    int*   smask = (int*)(rowc + 64);    // 64

    const int tid = threadIdx.x;
    const int wid = tid >> 5;
    const int wr  = wid >> 1;            // 0..3: 16-row strip
    const int wc  = wid & 1;             // 0..1: 32-col half
    const int q0  = blockIdx.x * 64;
    const int h   = blockIdx.y;
    const int b   = blockIdx.z;
    const size_t off = ((size_t)(b * NH + h) * SS) << 6;
    const float scaleF = 0.125f;         // HD^-0.5

    // load Q tile
    #pragma unroll
    for (int i = 0; i < 4; i++) {
        int lin = tid + i * 256;
        int r = lin >> 4;
        int c4 = (lin & 15) << 2;
        float4 v = *reinterpret_cast<const float4*>(&Q[off + ((size_t)(q0 + r) << 6) + c4]);
        sQ[r * 68 + c4 + 0] = v.x; sQ[r * 68 + c4 + 1] = v.y;
        sQ[r * 68 + c4 + 2] = v.z; sQ[r * 68 + c4 + 3] = v.w;
    }
    for (int i = tid; i < 64 * 68; i += 256) sO[i] = 0.0f;
    if (tid < 64) { rowm[tid] = -INFINITY; rowl[tid] = 0.0f; }
    __syncthreads();

    const int rr    = tid >> 2;      // row 0..63
    const int qd    = tid & 3;       // quarter of the row
    const int cbase = qd * 16;

    for (int kt = 0; kt < SS / 64; kt++) {
        const int k0 = kt * 64;
        // load K, V tiles
        #pragma unroll
        for (int i = 0; i < 4; i++) {
            int lin = tid + i * 256;
            int r = lin >> 4;
            int c4 = (lin & 15) << 2;
            float4 vk = *reinterpret_cast<const float4*>(&Kg[off + ((size_t)(k0 + r) << 6) + c4]);
            sK[r * 68 + c4 + 0] = vk.x; sK[r * 68 + c4 + 1] = vk.y;
            sK[r * 68 + c4 + 2] = vk.z; sK[r * 68 + c4 + 3] = vk.w;
            float4 vv = *reinterpret_cast<const float4*>(&Vg[off + ((size_t)(k0 + r) << 6) + c4]);
            sV[r * 68 + c4 + 0] = vv.x; sV[r * 68 + c4 + 1] = vv.y;
            sV[r * 68 + c4 + 2] = vv.z; sV[r * 68 + c4 + 3] = vv.w;
        }
        if (tid < 64) smask[tid] = maskg[b * SS + k0 + tid];
        __syncthreads();

        // ---- S = Q @ K^T ----
        {
            wmma::fragment<wmma::accumulator, 16, 16, 8, float> sacc[2];
            wmma::fill_fragment(sacc[0], 0.0f);
            wmma::fill_fragment(sacc[1], 0.0f);
            #pragma unroll
            for (int ks = 0; ks < 8; ks++) {
                wmma::fragment<wmma::matrix_a, 16, 16, 8, wmma::precision::tf32, wmma::row_major> af;
                wmma::load_matrix_sync(af, &sQ[wr * 16 * 68 + ks * 8], 68);
                #pragma unroll
                for (int t = 0; t < af.num_elements; t++)
                    af.x[t] = wmma::__float_to_tf32(af.x[t]);
                #pragma unroll
                for (int j = 0; j < 2; j++) {
                    wmma::fragment<wmma::matrix_b, 16, 16, 8, wmma::precision::tf32, wmma::col_major> bf;
                    wmma::load_matrix_sync(bf, &sK[(wc * 32 + j * 16) * 68 + ks * 8], 68);
                    #pragma unroll
                    for (int t = 0; t < bf.num_elements; t++)
                        bf.x[t] = wmma::__float_to_tf32(bf.x[t]);
                    wmma::mma_sync(sacc[j], af, bf, sacc[j]);
                }
            }
            #pragma unroll
            for (int j = 0; j < 2; j++)
                wmma::store_matrix_sync(&sS[wr * 16 * 68 + wc * 32 + j * 16], sacc[j], 68,
                                        wmma::mem_row_major);
        }
        __syncthreads();

        // ---- online softmax (4 threads per row) ----
        {
            float x[16];
            float mloc = -INFINITY;
            #pragma unroll
            for (int c = 0; c < 16; c++) {
                float v = sS[rr * 68 + cbase + c] * scaleF;
                v = fminf(fmaxf(v, -10000.0f), 10000.0f);
                if (smask[cbase + c] == 0) v = -1e30f;
                x[c] = v;
                mloc = fmaxf(mloc, v);
            }
            mloc = fmaxf(mloc, __shfl_xor_sync(0xffffffffu, mloc, 1));
            mloc = fmaxf(mloc, __shfl_xor_sync(0xffffffffu, mloc, 2));
            float mold = rowm[rr];
            float mnew = fmaxf(mold, mloc);
            float corr = __expf(mold - mnew);
            float ssum = 0.0f;
            #pragma unroll
            for (int c = 0; c < 16; c++) {
                float p = __expf(x[c] - mnew);
                sS[rr * 68 + cbase + c] = p;
                ssum += p;
            }
            ssum += __shfl_xor_sync(0xffffffffu, ssum, 1);
            ssum += __shfl_xor_sync(0xffffffffu, ssum, 2);
            if (qd == 0) {
                rowm[rr] = mnew;
                rowl[rr] = rowl[rr] * corr + ssum;
                rowc[rr] = corr;
            }
        }
        __syncthreads();

        // ---- PV = P @ V (result into sK alias) ----
        {
            wmma::fragment<wmma::accumulator, 16, 16, 8, float> pacc[2];
            wmma::fill_fragment(pacc[0], 0.0f);
            wmma::fill_fragment(pacc[1], 0.0f);
            #pragma unroll
            for (int ks = 0; ks < 8; ks++) {
                wmma::fragment<wmma::matrix_a, 16, 16, 8, wmma::precision::tf32, wmma::row_major> af;
                wmma::load_matrix_sync(af, &sS[wr * 16 * 68 + ks * 8], 68);
                #pragma unroll
                for (int t = 0; t < af.num_elements; t++)
                    af.x[t] = wmma::__float_to_tf32(af.x[t]);
                #pragma unroll
                for (int j = 0; j < 2; j++) {
                    wmma::fragment<wmma::matrix_b, 16, 16, 8, wmma::precision::tf32, wmma::row_major> bf;
                    wmma::load_matrix_sync(bf, &sV[(ks * 8) * 68 + wc * 32 + j * 16], 68);
                    #pragma unroll
                    for (int t = 0; t < bf.num_elements; t++)
                        bf.x[t] = wmma::__float_to_tf32(bf.x[t]);
                    wmma::mma_sync(pacc[j], af, bf, pacc[j]);
                }
            }
            #pragma unroll
            for (int j = 0; j < 2; j++)
                wmma::store_matrix_sync(&sK[wr * 16 * 68 + wc * 32 + j * 16], pacc[j], 68,
                                        wmma::mem_row_major);
        }
        __syncthreads();

        // ---- merge: sO = sO*corr + PV ----
        {
            float corr = rowc[rr];
            #pragma unroll
            for (int c = 0; c < 16; c++) {
                int idx = rr * 68 + cbase + c;
                sO[idx] = sO[idx] * corr + sK[idx];
            }
        }
        __syncthreads();
    }

    // write context [B, S, H]
    {
        float invl = 1.0f / rowl[rr];
        #pragma unroll
        for (int c = 0; c < 16; c++) {
            CTX[(size_t)(b * SS + q0 + rr) * HH + h * HD + cbase + c] =
                sO[rr * 68 + cbase + c] * invl;
        }
    }
}

// =================================================================
extern "C" void kernel_launch(void* const* d_in, const int* in_sizes, int n_in,
                              void* d_out, int out_size)
{
    const float* X    = (const float*)d_in[0];
    const int*   mask = (const int*)d_in[1];
    const float* WQ   = (const float*)d_in[2];
    const float* WK   = (const float*)d_in[3];
    const float* WV   = (const float*)d_in[4];
    const float* WO   = (const float*)d_in[5];
    float* out = (float*)d_out;

    float *qb, *kb, *vb, *cb;
    cudaGetSymbolAddress((void**)&qb, g_Q);
    cudaGetSymbolAddress((void**)&kb, g_K);
    cudaGetSymbolAddress((void**)&vb, g_V);
    cudaGetSymbolAddress((void**)&cb, g_CTX);

    dim3 gg(HH / 128, MROWS / 128);   // (8, 32)
    gemm128_tf32<<<gg, 256>>>(X, WQ, qb, MROWS, HH, HH, 1);
    gemm128_tf32<<<gg, 256>>>(X, WK, kb, MROWS, HH, HH, 1);
    gemm128_tf32<<<gg, 256>>>(X, WV, vb, MROWS, HH, HH, 1);

    size_t smem = (size_t)(5 * 64 * 68 + 3 * 64) * sizeof(float) + 64 * sizeof(int);
    cudaFuncSetAttribute(attn_kernel, cudaFuncAttributeMaxDynamicSharedMemorySize, (int)smem);
    attn_kernel<<<dim3(SS / 64, NH, BB), 256, smem>>>(qb, kb, vb, mask, cb);

    gemm128_tf32<<<gg, 256>>>(cb, WO, out, MROWS, HH, HH, 0);
}

// round 6
// speedup vs baseline: 1.5140x; 1.5140x over previous
#include <cuda_runtime.h>
#include <cuda_bf16.h>
#include <mma.h>
#include <math.h>
#include <stdint.h>

using namespace nvcuda;

#define BB  2
#define SS  2048
#define HH  1024
#define NHH 16
#define HD  64
#define MROWS (BB*SS)      // 4096

#define QTILE 128
#define KTILE 64

// ---------------- scratch (no allocations allowed) ----------------
__device__ float g_Q[(size_t)BB*SS*HH];
__device__ float g_K[(size_t)BB*SS*HH];
__device__ float g_V[(size_t)BB*SS*HH];
__device__ float g_CTX[(size_t)BB*SS*HH];

// =================================================================
// helpers
// =================================================================
__device__ __forceinline__ uint32_t f2tf32(float x) {
    uint32_t u;
    asm("cvt.rna.tf32.f32 %0, %1;" : "=r"(u) : "f"(x));
    return u;
}
__device__ __forceinline__ void mma_tf32_16n8k8(float* c,
    uint32_t a0, uint32_t a1, uint32_t a2, uint32_t a3,
    uint32_t b0, uint32_t b1)
{
    asm volatile("mma.sync.aligned.m16n8k8.row.col.f32.tf32.tf32.f32 "
        "{%0,%1,%2,%3},{%4,%5,%6,%7},{%8,%9},{%0,%1,%2,%3};"
        : "+f"(c[0]), "+f"(c[1]), "+f"(c[2]), "+f"(c[3])
        : "r"(a0), "r"(a1), "r"(a2), "r"(a3), "r"(b0), "r"(b1));
}
// column permutation within each 8-block so (c, c+4) pairs sit adjacent:
// p: 0,1,2,3,4,5,6,7 -> 0,2,4,6,1,3,5,7
__device__ __forceinline__ int permc(int h) {
    return (h & ~7) | ((h & 3) << 1) | ((h >> 2) & 1);
}

// =================================================================
// GEMM: C[M,N] = A[M,K] @ W[K,N], tf32 wmma, 128x128 block tile.
// permuted=1: write C to [B, NH, S, HD] layout (for Q/K/V).
// =================================================================
__global__ __launch_bounds__(256) void gemm128_tf32(
    const float* __restrict__ A, const float* __restrict__ Wm,
    float* __restrict__ C, int M, int N, int Kd, int permuted)
{
    __shared__ float sA[128][36];
    __shared__ float sB[32][132];

    const int tid = threadIdx.x;
    const int wid = tid >> 5;
    const int wm  = wid >> 2;
    const int wn  = wid & 3;
    const int m0  = blockIdx.y * 128;
    const int n0  = blockIdx.x * 128;

    wmma::fragment<wmma::accumulator, 16, 16, 8, float> acc[4][2];
    #pragma unroll
    for (int i = 0; i < 4; i++)
        #pragma unroll
        for (int j = 0; j < 2; j++)
            wmma::fill_fragment(acc[i][j], 0.0f);

    for (int kk = 0; kk < Kd; kk += 32) {
        #pragma unroll
        for (int i = 0; i < 4; i++) {
            int lin = tid + i * 256;
            int r = lin >> 3;
            int c4 = (lin & 7) << 2;
            float4 v = *reinterpret_cast<const float4*>(&A[(size_t)(m0 + r) * Kd + kk + c4]);
            sA[r][c4 + 0] = v.x; sA[r][c4 + 1] = v.y;
            sA[r][c4 + 2] = v.z; sA[r][c4 + 3] = v.w;
        }
        #pragma unroll
        for (int i = 0; i < 4; i++) {
            int lin = tid + i * 256;
            int r = lin >> 5;
            int c4 = (lin & 31) << 2;
            float4 v = *reinterpret_cast<const float4*>(&Wm[(size_t)(kk + r) * N + n0 + c4]);
            sB[r][c4 + 0] = v.x; sB[r][c4 + 1] = v.y;
            sB[r][c4 + 2] = v.z; sB[r][c4 + 3] = v.w;
        }
        __syncthreads();

        #pragma unroll
        for (int ks = 0; ks < 4; ks++) {
            wmma::fragment<wmma::matrix_a, 16, 16, 8, wmma::precision::tf32, wmma::row_major> af[4];
            wmma::fragment<wmma::matrix_b, 16, 16, 8, wmma::precision::tf32, wmma::row_major> bf[2];
            #pragma unroll
            for (int i = 0; i < 4; i++) {
                wmma::load_matrix_sync(af[i], &sA[wm * 64 + i * 16][ks * 8], 36);
                #pragma unroll
                for (int t = 0; t < af[i].num_elements; t++)
                    af[i].x[t] = wmma::__float_to_tf32(af[i].x[t]);
            }
            #pragma unroll
            for (int j = 0; j < 2; j++) {
                wmma::load_matrix_sync(bf[j], &sB[ks * 8][wn * 32 + j * 16], 132);
                #pragma unroll
                for (int t = 0; t < bf[j].num_elements; t++)
                    bf[j].x[t] = wmma::__float_to_tf32(bf[j].x[t]);
            }
            #pragma unroll
            for (int i = 0; i < 4; i++)
                #pragma unroll
                for (int j = 0; j < 2; j++)
                    wmma::mma_sync(acc[i][j], af[i], bf[j], acc[i][j]);
        }
        __syncthreads();
    }

    #pragma unroll
    for (int i = 0; i < 4; i++) {
        #pragma unroll
        for (int j = 0; j < 2; j++) {
            int r0 = m0 + wm * 64 + i * 16;
            int c0 = n0 + wn * 32 + j * 16;
            if (permuted) {
                int b  = r0 >> 11;
                int s  = r0 & (SS - 1);
                int h  = c0 >> 6;
                int hd = c0 & (HD - 1);
                float* p = C + (((size_t)(b * NHH + h) * SS + s) << 6) + hd;
                wmma::store_matrix_sync(p, acc[i][j], HD, wmma::mem_row_major);
            } else {
                wmma::store_matrix_sync(C + (size_t)r0 * N + c0, acc[i][j], N, wmma::mem_row_major);
            }
        }
    }
}

// =================================================================
// Flash attention, register-resident (FA2 style, raw mma.sync).
// 128 query rows / CTA (8 warps x 16 rows), 64-key tiles.
// QK^T and PV both tf32 m16n8k8; P moved C-layout -> A-layout by
// quad shuffles (no smem round trip).
// =================================================================
__global__ __launch_bounds__(256, 2) void attn_kernel(
    const float* __restrict__ Q, const float* __restrict__ Kg,
    const float* __restrict__ Vg, const int* __restrict__ maskg,
    float* __restrict__ CTX)
{
    extern __shared__ float smbuf[];
    float* sQ = smbuf;                       // [128][68], permuted cols
    float* sK = sQ + 128 * 68;               // [64][68], permuted cols
    float* sV = sK + 64 * 68;                // [64 keys][72 hd-padded]
    float* sBias = sV + 64 * 72;             // [64]

    const int tid  = threadIdx.x;
    const int wid  = tid >> 5;
    const int lane = tid & 31;
    const int gi   = lane >> 2;   // group id 0..7
    const int ti   = lane & 3;    // thread in group 0..3
    const int q0   = blockIdx.x * QTILE;
    const int h    = blockIdx.y;
    const int b    = blockIdx.z;
    const size_t off = ((size_t)(b * NHH + h) * SS) << 6;
    const float scaleF = 0.125f;

    // ---- load Q tile (128x64) into permuted smem ----
    #pragma unroll
    for (int i = 0; i < 8; i++) {
        int lin = tid + i * 256;
        int r = lin >> 4;
        int c4 = (lin & 15) << 2;
        float4 v = *reinterpret_cast<const float4*>(&Q[off + ((size_t)(q0 + r) << 6) + c4]);
        sQ[r * 68 + permc(c4 + 0)] = v.x;
        sQ[r * 68 + permc(c4 + 1)] = v.y;
        sQ[r * 68 + permc(c4 + 2)] = v.z;
        sQ[r * 68 + permc(c4 + 3)] = v.w;
    }

    // per-thread state: rows r0 = wid*16+gi, r1 = r0+8
    float o[8][4];
    #pragma unroll
    for (int j = 0; j < 8; j++)
        #pragma unroll
        for (int e = 0; e < 4; e++) o[j][e] = 0.0f;
    float m0 = -INFINITY, m1 = -INFINITY;
    float l0 = 0.0f, l1 = 0.0f;

    const int ar0 = wid * 16 + gi;

    for (int kt = 0; kt < SS / KTILE; kt++) {
        const int k0 = kt * KTILE;

        // ---- load K (permuted) and V (fp32, padded) tiles ----
        #pragma unroll
        for (int i = 0; i < 4; i++) {
            int lin = tid + i * 256;
            int r = lin >> 4;
            int c4 = (lin & 15) << 2;
            float4 vk = *reinterpret_cast<const float4*>(&Kg[off + ((size_t)(k0 + r) << 6) + c4]);
            sK[r * 68 + permc(c4 + 0)] = vk.x;
            sK[r * 68 + permc(c4 + 1)] = vk.y;
            sK[r * 68 + permc(c4 + 2)] = vk.z;
            sK[r * 68 + permc(c4 + 3)] = vk.w;
            float4 vv = *reinterpret_cast<const float4*>(&Vg[off + ((size_t)(k0 + r) << 6) + c4]);
            *reinterpret_cast<float4*>(&sV[r * 72 + c4]) = vv;
        }
        if (tid < KTILE)
            sBias[tid] = (maskg[b * SS + k0 + tid] == 0) ? -1e30f : 0.0f;
        __syncthreads();

        // ---- S = Q @ K^T (tf32), scores stay in registers ----
        float s[8][4];
        #pragma unroll
        for (int j = 0; j < 8; j++)
            #pragma unroll
            for (int e = 0; e < 4; e++) s[j][e] = 0.0f;

        #pragma unroll
        for (int ks = 0; ks < 8; ks++) {
            float2 qa0 = *reinterpret_cast<const float2*>(&sQ[ar0 * 68 + ks * 8 + 2 * ti]);
            float2 qa1 = *reinterpret_cast<const float2*>(&sQ[(ar0 + 8) * 68 + ks * 8 + 2 * ti]);
            uint32_t a0 = f2tf32(qa0.x), a2 = f2tf32(qa0.y);
            uint32_t a1 = f2tf32(qa1.x), a3 = f2tf32(qa1.y);
            #pragma unroll
            for (int j = 0; j < 8; j++) {
                float2 kb = *reinterpret_cast<const float2*>(&sK[(j * 8 + gi) * 68 + ks * 8 + 2 * ti]);
                mma_tf32_16n8k8(s[j], a0, a1, a2, a3, f2tf32(kb.x), f2tf32(kb.y));
            }
        }

        // ---- online softmax in registers ----
        float mloc0 = -INFINITY, mloc1 = -INFINITY;
        #pragma unroll
        for (int j = 0; j < 8; j++) {
            float b0 = sBias[j * 8 + 2 * ti];
            float b1 = sBias[j * 8 + 2 * ti + 1];
            s[j][0] = fminf(fmaxf(s[j][0] * scaleF, -10000.0f), 10000.0f) + b0;
            s[j][1] = fminf(fmaxf(s[j][1] * scaleF, -10000.0f), 10000.0f) + b1;
            s[j][2] = fminf(fmaxf(s[j][2] * scaleF, -10000.0f), 10000.0f) + b0;
            s[j][3] = fminf(fmaxf(s[j][3] * scaleF, -10000.0f), 10000.0f) + b1;
            mloc0 = fmaxf(mloc0, fmaxf(s[j][0], s[j][1]));
            mloc1 = fmaxf(mloc1, fmaxf(s[j][2], s[j][3]));
        }
        mloc0 = fmaxf(mloc0, __shfl_xor_sync(0xffffffffu, mloc0, 1));
        mloc0 = fmaxf(mloc0, __shfl_xor_sync(0xffffffffu, mloc0, 2));
        mloc1 = fmaxf(mloc1, __shfl_xor_sync(0xffffffffu, mloc1, 1));
        mloc1 = fmaxf(mloc1, __shfl_xor_sync(0xffffffffu, mloc1, 2));

        float mn0 = fmaxf(m0, mloc0);
        float mn1 = fmaxf(m1, mloc1);
        float corr0 = __expf(m0 - mn0);
        float corr1 = __expf(m1 - mn1);
        m0 = mn0; m1 = mn1;

        float sum0 = 0.0f, sum1 = 0.0f;
        #pragma unroll
        for (int j = 0; j < 8; j++) {
            s[j][0] = __expf(s[j][0] - mn0);
            s[j][1] = __expf(s[j][1] - mn0);
            s[j][2] = __expf(s[j][2] - mn1);
            s[j][3] = __expf(s[j][3] - mn1);
            sum0 += s[j][0] + s[j][1];
            sum1 += s[j][2] + s[j][3];
        }
        sum0 += __shfl_xor_sync(0xffffffffu, sum0, 1);
        sum0 += __shfl_xor_sync(0xffffffffu, sum0, 2);
        sum1 += __shfl_xor_sync(0xffffffffu, sum1, 1);
        sum1 += __shfl_xor_sync(0xffffffffu, sum1, 2);
        l0 = l0 * corr0 + sum0;
        l1 = l1 * corr1 + sum1;

        // rescale O
        #pragma unroll
        for (int j = 0; j < 8; j++) {
            o[j][0] *= corr0; o[j][1] *= corr0;
            o[j][2] *= corr1; o[j][3] *= corr1;
        }

        // ---- O += P @ V (tf32 mma, P shuffled C-layout -> A-layout) ----
        {
            const int qb   = lane & ~3;
            const int src0 = qb + (ti >> 1);
            const int src1 = src0 + 2;
            const bool odd = (ti & 1);
            #pragma unroll
            for (int kb = 0; kb < 8; kb++) {
                float v00 = __shfl_sync(0xffffffffu, s[kb][0], src0);
                float v01 = __shfl_sync(0xffffffffu, s[kb][1], src0);
                float v20 = __shfl_sync(0xffffffffu, s[kb][0], src1);
                float v21 = __shfl_sync(0xffffffffu, s[kb][1], src1);
                float v10 = __shfl_sync(0xffffffffu, s[kb][2], src0);
                float v11 = __shfl_sync(0xffffffffu, s[kb][3], src0);
                float v30 = __shfl_sync(0xffffffffu, s[kb][2], src1);
                float v31 = __shfl_sync(0xffffffffu, s[kb][3], src1);
                uint32_t a0 = f2tf32(odd ? v01 : v00);   // (row gi,   col kb*8+ti)
                uint32_t a1 = f2tf32(odd ? v11 : v10);   // (row gi+8, col kb*8+ti)
                uint32_t a2 = f2tf32(odd ? v21 : v20);   // (row gi,   col kb*8+ti+4)
                uint32_t a3 = f2tf32(odd ? v31 : v30);   // (row gi+8, col kb*8+ti+4)
                #pragma unroll
                for (int j = 0; j < 8; j++) {
                    float bv0 = sV[(kb * 8 + ti) * 72 + j * 8 + gi];
                    float bv1 = sV[(kb * 8 + ti + 4) * 72 + j * 8 + gi];
                    mma_tf32_16n8k8(o[j], a0, a1, a2, a3, f2tf32(bv0), f2tf32(bv1));
                }
            }
        }
        __syncthreads();
    }

    // ---- normalize and write context [B, S, H] ----
    float inv0 = 1.0f / l0;
    float inv1 = 1.0f / l1;
    int row0 = q0 + wid * 16 + gi;
    #pragma unroll
    for (int j = 0; j < 8; j++) {
        float2 v0 = make_float2(o[j][0] * inv0, o[j][1] * inv0);
        float2 v1 = make_float2(o[j][2] * inv1, o[j][3] * inv1);
        *reinterpret_cast<float2*>(
            &CTX[(size_t)(b * SS + row0) * HH + h * HD + j * 8 + 2 * ti]) = v0;
        *reinterpret_cast<float2*>(
            &CTX[(size_t)(b * SS + row0 + 8) * HH + h * HD + j * 8 + 2 * ti]) = v1;
    }
}

// =================================================================
extern "C" void kernel_launch(void* const* d_in, const int* in_sizes, int n_in,
                              void* d_out, int out_size)
{
    const float* X    = (const float*)d_in[0];
    const int*   mask = (const int*)d_in[1];
    const float* WQ   = (const float*)d_in[2];
    const float* WK   = (const float*)d_in[3];
    const float* WV   = (const float*)d_in[4];
    const float* WO   = (const float*)d_in[5];
    float* out = (float*)d_out;

    float *qb, *kb, *vb, *cb;
    cudaGetSymbolAddress((void**)&qb, g_Q);
    cudaGetSymbolAddress((void**)&kb, g_K);
    cudaGetSymbolAddress((void**)&vb, g_V);
    cudaGetSymbolAddress((void**)&cb, g_CTX);

    dim3 gg(HH / 128, MROWS / 128);   // (8, 32)
    gemm128_tf32<<<gg, 256>>>(X, WQ, qb, MROWS, HH, HH, 1);
    gemm128_tf32<<<gg, 256>>>(X, WK, kb, MROWS, HH, HH, 1);
    gemm128_tf32<<<gg, 256>>>(X, WV, vb, MROWS, HH, HH, 1);

    size_t smem = (size_t)(128 * 68 + 64 * 68 + 64 * 72 + 64) * sizeof(float);
    cudaFuncSetAttribute(attn_kernel, cudaFuncAttributeMaxDynamicSharedMemorySize, (int)smem);
    attn_kernel<<<dim3(SS / QTILE, NHH, BB), 256, smem>>>(qb, kb, vb, mask, cb);

    gemm128_tf32<<<gg, 256>>>(cb, WO, out, MROWS, HH, HH, 0);
}

// round 7
// speedup vs baseline: 1.9008x; 1.2555x over previous
#include <cuda_runtime.h>
#include <cuda_bf16.h>
#include <math.h>
#include <stdint.h>

#define BB  2
#define SS  2048
#define HH  1024
#define NHH 16
#define HD  64
#define MROWS (BB*SS)      // 4096
#define GK  1024           // inner dim of all projections

#define QTILE 128
#define KTILE 64

// ---------------- scratch (no allocations allowed) ----------------
__device__ float g_Q[(size_t)BB*SS*HH];
__device__ float g_K[(size_t)BB*SS*HH];
__device__ float g_V[(size_t)BB*SS*HH];
__device__ float g_CTX[(size_t)BB*SS*HH];

// =================================================================
// helpers
// =================================================================
__device__ __forceinline__ uint32_t f2tf32(float x) {
    uint32_t u;
    asm("cvt.rna.tf32.f32 %0, %1;" : "=r"(u) : "f"(x));
    return u;
}
__device__ __forceinline__ float cvtf(float x) {           // tf32 bits as float
    return __uint_as_float(f2tf32(x));
}
__device__ __forceinline__ void mma_tf32_16n8k8(float* c,
    uint32_t a0, uint32_t a1, uint32_t a2, uint32_t a3,
    uint32_t b0, uint32_t b1)
{
    asm volatile("mma.sync.aligned.m16n8k8.row.col.f32.tf32.tf32.f32 "
        "{%0,%1,%2,%3},{%4,%5,%6,%7},{%8,%9},{%0,%1,%2,%3};"
        : "+f"(c[0]), "+f"(c[1]), "+f"(c[2]), "+f"(c[3])
        : "r"(a0), "r"(a1), "r"(a2), "r"(a3), "r"(b0), "r"(b1));
}
// column permutation within each 8-block so logical (c, c+4) sit adjacent:
// 0,1,2,3,4,5,6,7 -> 0,2,4,6,1,3,5,7
__device__ __forceinline__ int permc(int h) {
    return (h & ~7) | ((h & 3) << 1) | ((h >> 2) & 1);
}

// =================================================================
// GEMM: C[4096,1024] = A[4096,1024] @ W[1024,1024], raw mma tf32.
// 128x128 CTA tile, 64x32 warp tile, double-buffered smem,
// tf32 conversion at smem-store, register-staged global loads.
// permuted=1: write C to [B, NH, S, HD] layout (for Q/K/V).
// =================================================================
#define SA_STRIDE 36
#define SB_STRIDE 136
#define SA_BUF (128 * SA_STRIDE)
#define SB_BUF (32 * SB_STRIDE)

__global__ __launch_bounds__(256) void gemm_tf32_mma(
    const float* __restrict__ A, const float* __restrict__ Wm,
    float* __restrict__ C, int permuted)
{
    extern __shared__ float sm[];
    float* sA = sm;                  // 2 x [128][36]
    float* sB = sm + 2 * SA_BUF;     // 2 x [32][136]

    const int tid  = threadIdx.x;
    const int wid  = tid >> 5;
    const int lane = tid & 31;
    const int gi   = lane >> 2;
    const int ti   = lane & 3;
    const int wm   = wid >> 2;       // 0..1
    const int wn   = wid & 3;        // 0..3
    const int m0   = blockIdx.y * 128;
    const int n0   = blockIdx.x * 128;

    // global staging indices
    const int arow = tid >> 3;              // +32*i
    const int acol = (tid & 7) << 2;
    const int brow = tid >> 5;              // +8*i
    const int bcol = (tid & 31) << 2;
    const float* Aptr = A + (size_t)(m0 + arow) * GK + acol;
    const float* Bptr = Wm + (size_t)brow * HH + n0 + bcol;

    float acc[4][4][4];
    #pragma unroll
    for (int mi = 0; mi < 4; mi++)
        #pragma unroll
        for (int ni = 0; ni < 4; ni++)
            #pragma unroll
            for (int e = 0; e < 4; e++) acc[mi][ni][e] = 0.0f;

    float4 ra[4], rb[4];

    // ---- prologue: tile 0 ----
    #pragma unroll
    for (int i = 0; i < 4; i++) {
        ra[i] = *reinterpret_cast<const float4*>(Aptr + (size_t)(32 * i) * GK);
        rb[i] = *reinterpret_cast<const float4*>(Bptr + (size_t)(8 * i) * HH);
    }
    {
        float* sAb = sA;
        float* sBb = sB;
        #pragma unroll
        for (int i = 0; i < 4; i++) {
            float* d = &sAb[(arow + 32 * i) * SA_STRIDE];
            d[permc(acol + 0)] = cvtf(ra[i].x);
            d[permc(acol + 1)] = cvtf(ra[i].y);
            d[permc(acol + 2)] = cvtf(ra[i].z);
            d[permc(acol + 3)] = cvtf(ra[i].w);
            float4 t;
            t.x = cvtf(rb[i].x); t.y = cvtf(rb[i].y);
            t.z = cvtf(rb[i].z); t.w = cvtf(rb[i].w);
            *reinterpret_cast<float4*>(&sBb[(brow + 8 * i) * SB_STRIDE + bcol]) = t;
        }
    }
    __syncthreads();

    int buf = 0;
    const int NKT = GK / 32;   // 32
    for (int kt = 0; kt < NKT; kt++) {
        // issue global loads for next tile
        if (kt + 1 < NKT) {
            const int kk = (kt + 1) * 32;
            #pragma unroll
            for (int i = 0; i < 4; i++) {
                ra[i] = *reinterpret_cast<const float4*>(Aptr + kk + (size_t)(32 * i) * GK);
                rb[i] = *reinterpret_cast<const float4*>(Bptr + (size_t)(kk + 8 * i) * HH);
            }
        }

        // compute current buffer
        const float* sAc = sA + buf * SA_BUF;
        const float* sBc = sB + buf * SB_BUF;
        #pragma unroll
        for (int ks = 0; ks < 4; ks++) {
            uint32_t af[4][4];
            #pragma unroll
            for (int mi = 0; mi < 4; mi++) {
                int row = wm * 64 + mi * 16 + gi;
                float2 lo = *reinterpret_cast<const float2*>(&sAc[row * SA_STRIDE + ks * 8 + 2 * ti]);
                float2 hi = *reinterpret_cast<const float2*>(&sAc[(row + 8) * SA_STRIDE + ks * 8 + 2 * ti]);
                af[mi][0] = __float_as_uint(lo.x);
                af[mi][1] = __float_as_uint(hi.x);
                af[mi][2] = __float_as_uint(lo.y);
                af[mi][3] = __float_as_uint(hi.y);
            }
            #pragma unroll
            for (int ni = 0; ni < 4; ni++) {
                int nc = wn * 32 + ni * 8 + gi;
                uint32_t b0 = __float_as_uint(sBc[(ks * 8 + ti) * SB_STRIDE + nc]);
                uint32_t b1 = __float_as_uint(sBc[(ks * 8 + ti + 4) * SB_STRIDE + nc]);
                #pragma unroll
                for (int mi = 0; mi < 4; mi++)
                    mma_tf32_16n8k8(acc[mi][ni], af[mi][0], af[mi][1], af[mi][2], af[mi][3], b0, b1);
            }
        }

        // stage next tile into alternate buffer
        if (kt + 1 < NKT) {
            float* sAb = sA + (buf ^ 1) * SA_BUF;
            float* sBb = sB + (buf ^ 1) * SB_BUF;
            #pragma unroll
            for (int i = 0; i < 4; i++) {
                float* d = &sAb[(arow + 32 * i) * SA_STRIDE];
                d[permc(acol + 0)] = cvtf(ra[i].x);
                d[permc(acol + 1)] = cvtf(ra[i].y);
                d[permc(acol + 2)] = cvtf(ra[i].z);
                d[permc(acol + 3)] = cvtf(ra[i].w);
                float4 t;
                t.x = cvtf(rb[i].x); t.y = cvtf(rb[i].y);
                t.z = cvtf(rb[i].z); t.w = cvtf(rb[i].w);
                *reinterpret_cast<float4*>(&sBb[(brow + 8 * i) * SB_STRIDE + bcol]) = t;
            }
            __syncthreads();
            buf ^= 1;
        }
    }

    // ---- epilogue ----
    #pragma unroll
    for (int mi = 0; mi < 4; mi++) {
        #pragma unroll
        for (int ni = 0; ni < 4; ni++) {
            int r0 = m0 + wm * 64 + mi * 16 + gi;   // row of c0/c1
            int c0 = n0 + wn * 32 + ni * 8 + 2 * ti;
            if (permuted) {
                int b  = r0 >> 11;
                int s  = r0 & (SS - 1);
                int h  = c0 >> 6;
                int hd = c0 & (HD - 1);
                float* p0 = C + (((size_t)(b * NHH + h) * SS + s) << 6) + hd;
                *reinterpret_cast<float2*>(p0) = make_float2(acc[mi][ni][0], acc[mi][ni][1]);
                int r1 = r0 + 8;
                int s1 = r1 & (SS - 1);
                int b1 = r1 >> 11;
                float* p1 = C + (((size_t)(b1 * NHH + h) * SS + s1) << 6) + hd;
                *reinterpret_cast<float2*>(p1) = make_float2(acc[mi][ni][2], acc[mi][ni][3]);
            } else {
                *reinterpret_cast<float2*>(&C[(size_t)r0 * HH + c0]) =
                    make_float2(acc[mi][ni][0], acc[mi][ni][1]);
                *reinterpret_cast<float2*>(&C[(size_t)(r0 + 8) * HH + c0]) =
                    make_float2(acc[mi][ni][2], acc[mi][ni][3]);
            }
        }
    }
}

// =================================================================
// Flash attention, register-resident (FA2 style, raw mma.sync).
// Unchanged from R6 (409us, validated).
// =================================================================
__global__ __launch_bounds__(256, 2) void attn_kernel(
    const float* __restrict__ Q, const float* __restrict__ Kg,
    const float* __restrict__ Vg, const int* __restrict__ maskg,
    float* __restrict__ CTX)
{
    extern __shared__ float smbuf[];
    float* sQ = smbuf;                       // [128][68], permuted cols
    float* sK = sQ + 128 * 68;               // [64][68], permuted cols
    float* sV = sK + 64 * 68;                // [64 keys][72 hd-padded]
    float* sBias = sV + 64 * 72;             // [64]

    const int tid  = threadIdx.x;
    const int wid  = tid >> 5;
    const int lane = tid & 31;
    const int gi   = lane >> 2;
    const int ti   = lane & 3;
    const int q0   = blockIdx.x * QTILE;
    const int h    = blockIdx.y;
    const int b    = blockIdx.z;
    const size_t off = ((size_t)(b * NHH + h) * SS) << 6;
    const float scaleF = 0.125f;

    #pragma unroll
    for (int i = 0; i < 8; i++) {
        int lin = tid + i * 256;
        int r = lin >> 4;
        int c4 = (lin & 15) << 2;
        float4 v = *reinterpret_cast<const float4*>(&Q[off + ((size_t)(q0 + r) << 6) + c4]);
        sQ[r * 68 + permc(c4 + 0)] = v.x;
        sQ[r * 68 + permc(c4 + 1)] = v.y;
        sQ[r * 68 + permc(c4 + 2)] = v.z;
        sQ[r * 68 + permc(c4 + 3)] = v.w;
    }

    float o[8][4];
    #pragma unroll
    for (int j = 0; j < 8; j++)
        #pragma unroll
        for (int e = 0; e < 4; e++) o[j][e] = 0.0f;
    float m0 = -INFINITY, m1 = -INFINITY;
    float l0 = 0.0f, l1 = 0.0f;

    const int ar0 = wid * 16 + gi;

    for (int kt = 0; kt < SS / KTILE; kt++) {
        const int k0 = kt * KTILE;

        #pragma unroll
        for (int i = 0; i < 4; i++) {
            int lin = tid + i * 256;
            int r = lin >> 4;
            int c4 = (lin & 15) << 2;
            float4 vk = *reinterpret_cast<const float4*>(&Kg[off + ((size_t)(k0 + r) << 6) + c4]);
            sK[r * 68 + permc(c4 + 0)] = vk.x;
            sK[r * 68 + permc(c4 + 1)] = vk.y;
            sK[r * 68 + permc(c4 + 2)] = vk.z;
            sK[r * 68 + permc(c4 + 3)] = vk.w;
            float4 vv = *reinterpret_cast<const float4*>(&Vg[off + ((size_t)(k0 + r) << 6) + c4]);
            *reinterpret_cast<float4*>(&sV[r * 72 + c4]) = vv;
        }
        if (tid < KTILE)
            sBias[tid] = (maskg[b * SS + k0 + tid] == 0) ? -1e30f : 0.0f;
        __syncthreads();

        float s[8][4];
        #pragma unroll
        for (int j = 0; j < 8; j++)
            #pragma unroll
            for (int e = 0; e < 4; e++) s[j][e] = 0.0f;

        #pragma unroll
        for (int ks = 0; ks < 8; ks++) {
            float2 qa0 = *reinterpret_cast<const float2*>(&sQ[ar0 * 68 + ks * 8 + 2 * ti]);
            float2 qa1 = *reinterpret_cast<const float2*>(&sQ[(ar0 + 8) * 68 + ks * 8 + 2 * ti]);
            uint32_t a0 = f2tf32(qa0.x), a2 = f2tf32(qa0.y);
            uint32_t a1 = f2tf32(qa1.x), a3 = f2tf32(qa1.y);
            #pragma unroll
            for (int j = 0; j < 8; j++) {
                float2 kb = *reinterpret_cast<const float2*>(&sK[(j * 8 + gi) * 68 + ks * 8 + 2 * ti]);
                mma_tf32_16n8k8(s[j], a0, a1, a2, a3, f2tf32(kb.x), f2tf32(kb.y));
            }
        }

        float mloc0 = -INFINITY, mloc1 = -INFINITY;
        #pragma unroll
        for (int j = 0; j < 8; j++) {
            float b0 = sBias[j * 8 + 2 * ti];
            float b1 = sBias[j * 8 + 2 * ti + 1];
            s[j][0] = fminf(fmaxf(s[j][0] * scaleF, -10000.0f), 10000.0f) + b0;
            s[j][1] = fminf(fmaxf(s[j][1] * scaleF, -10000.0f), 10000.0f) + b1;
            s[j][2] = fminf(fmaxf(s[j][2] * scaleF, -10000.0f), 10000.0f) + b0;
            s[j][3] = fminf(fmaxf(s[j][3] * scaleF, -10000.0f), 10000.0f) + b1;
            mloc0 = fmaxf(mloc0, fmaxf(s[j][0], s[j][1]));
            mloc1 = fmaxf(mloc1, fmaxf(s[j][2], s[j][3]));
        }
        mloc0 = fmaxf(mloc0, __shfl_xor_sync(0xffffffffu, mloc0, 1));
        mloc0 = fmaxf(mloc0, __shfl_xor_sync(0xffffffffu, mloc0, 2));
        mloc1 = fmaxf(mloc1, __shfl_xor_sync(0xffffffffu, mloc1, 1));
        mloc1 = fmaxf(mloc1, __shfl_xor_sync(0xffffffffu, mloc1, 2));

        float mn0 = fmaxf(m0, mloc0);
        float mn1 = fmaxf(m1, mloc1);
        float corr0 = __expf(m0 - mn0);
        float corr1 = __expf(m1 - mn1);
        m0 = mn0; m1 = mn1;

        float sum0 = 0.0f, sum1 = 0.0f;
        #pragma unroll
        for (int j = 0; j < 8; j++) {
            s[j][0] = __expf(s[j][0] - mn0);
            s[j][1] = __expf(s[j][1] - mn0);
            s[j][2] = __expf(s[j][2] - mn1);
            s[j][3] = __expf(s[j][3] - mn1);
            sum0 += s[j][0] + s[j][1];
            sum1 += s[j][2] + s[j][3];
        }
        sum0 += __shfl_xor_sync(0xffffffffu, sum0, 1);
        sum0 += __shfl_xor_sync(0xffffffffu, sum0, 2);
        sum1 += __shfl_xor_sync(0xffffffffu, sum1, 1);
        sum1 += __shfl_xor_sync(0xffffffffu, sum1, 2);
        l0 = l0 * corr0 + sum0;
        l1 = l1 * corr1 + sum1;

        #pragma unroll
        for (int j = 0; j < 8; j++) {
            o[j][0] *= corr0; o[j][1] *= corr0;
            o[j][2] *= corr1; o[j][3] *= corr1;
        }

        {
            const int qb   = lane & ~3;
            const int src0 = qb + (ti >> 1);
            const int src1 = src0 + 2;
            const bool odd = (ti & 1);
            #pragma unroll
            for (int kb = 0; kb < 8; kb++) {
                float v00 = __shfl_sync(0xffffffffu, s[kb][0], src0);
                float v01 = __shfl_sync(0xffffffffu, s[kb][1], src0);
                float v20 = __shfl_sync(0xffffffffu, s[kb][0], src1);
                float v21 = __shfl_sync(0xffffffffu, s[kb][1], src1);
                float v10 = __shfl_sync(0xffffffffu, s[kb][2], src0);
                float v11 = __shfl_sync(0xffffffffu, s[kb][3], src0);
                float v30 = __shfl_sync(0xffffffffu, s[kb][2], src1);
                float v31 = __shfl_sync(0xffffffffu, s[kb][3], src1);
                uint32_t a0 = f2tf32(odd ? v01 : v00);
                uint32_t a1 = f2tf32(odd ? v11 : v10);
                uint32_t a2 = f2tf32(odd ? v21 : v20);
                uint32_t a3 = f2tf32(odd ? v31 : v30);
                #pragma unroll
                for (int j = 0; j < 8; j++) {
                    float bv0 = sV[(kb * 8 + ti) * 72 + j * 8 + gi];
                    float bv1 = sV[(kb * 8 + ti + 4) * 72 + j * 8 + gi];
                    mma_tf32_16n8k8(o[j], a0, a1, a2, a3, f2tf32(bv0), f2tf32(bv1));
                }
            }
        }
        __syncthreads();
    }

    float inv0 = 1.0f / l0;
    float inv1 = 1.0f / l1;
    int row0 = q0 + wid * 16 + gi;
    #pragma unroll
    for (int j = 0; j < 8; j++) {
        float2 v0 = make_float2(o[j][0] * inv0, o[j][1] * inv0);
        float2 v1 = make_float2(o[j][2] * inv1, o[j][3] * inv1);
        *reinterpret_cast<float2*>(
            &CTX[(size_t)(b * SS + row0) * HH + h * HD + j * 8 + 2 * ti]) = v0;
        *reinterpret_cast<float2*>(
            &CTX[(size_t)(b * SS + row0 + 8) * HH + h * HD + j * 8 + 2 * ti]) = v1;
    }
}

// =================================================================
extern "C" void kernel_launch(void* const* d_in, const int* in_sizes, int n_in,
                              void* d_out, int out_size)
{
    const float* X    = (const float*)d_in[0];
    const int*   mask = (const int*)d_in[1];
    const float* WQ   = (const float*)d_in[2];
    const float* WK   = (const float*)d_in[3];
    const float* WV   = (const float*)d_in[4];
    const float* WO   = (const float*)d_in[5];
    float* out = (float*)d_out;

    float *qb, *kb, *vb, *cb;
    cudaGetSymbolAddress((void**)&qb, g_Q);
    cudaGetSymbolAddress((void**)&kb, g_K);
    cudaGetSymbolAddress((void**)&vb, g_V);
    cudaGetSymbolAddress((void**)&cb, g_CTX);

    size_t gsmem = (size_t)(2 * SA_BUF + 2 * SB_BUF) * sizeof(float);  // ~71.7KB
    cudaFuncSetAttribute(gemm_tf32_mma, cudaFuncAttributeMaxDynamicSharedMemorySize, (int)gsmem);

    dim3 gg(HH / 128, MROWS / 128);   // (8, 32)
    gemm_tf32_mma<<<gg, 256, gsmem>>>(X, WQ, qb, 1);
    gemm_tf32_mma<<<gg, 256, gsmem>>>(X, WK, kb, 1);
    gemm_tf32_mma<<<gg, 256, gsmem>>>(X, WV, vb, 1);

    size_t smem = (size_t)(128 * 68 + 64 * 68 + 64 * 72 + 64) * sizeof(float);
    cudaFuncSetAttribute(attn_kernel, cudaFuncAttributeMaxDynamicSharedMemorySize, (int)smem);
    attn_kernel<<<dim3(SS / QTILE, NHH, BB), 256, smem>>>(qb, kb, vb, mask, cb);

    gemm_tf32_mma<<<gg, 256, gsmem>>>(cb, WO, out, 0);
}

// round 9
// speedup vs baseline: 2.1626x; 1.1378x over previous
#include <cuda_runtime.h>
#include <cuda_bf16.h>
#include <math.h>
#include <stdint.h>

#define BB  2
#define SS  2048
#define HH  1024
#define NHH 16
#define HD  64
#define MROWS (BB*SS)      // 4096
#define GK  1024           // inner dim of all projections

#define QTILE 128
#define KTILE 64

// ---------------- scratch (no allocations allowed) ----------------
__device__ float g_Q[(size_t)BB*SS*HH];
__device__ float g_K[(size_t)BB*SS*HH];
__device__ float g_V[(size_t)BB*SS*HH];
__device__ float g_CTX[(size_t)BB*SS*HH];

// =================================================================
// helpers
// =================================================================
__device__ __forceinline__ uint32_t f2tf32(float x) {
    uint32_t u;
    asm("cvt.rna.tf32.f32 %0, %1;" : "=r"(u) : "f"(x));
    return u;
}
__device__ __forceinline__ float cvtf(float x) {           // tf32 bits as float
    return __uint_as_float(f2tf32(x));
}
__device__ __forceinline__ void mma_tf32_16n8k8(float* c,
    uint32_t a0, uint32_t a1, uint32_t a2, uint32_t a3,
    uint32_t b0, uint32_t b1)
{
    asm volatile("mma.sync.aligned.m16n8k8.row.col.f32.tf32.tf32.f32 "
        "{%0,%1,%2,%3},{%4,%5,%6,%7},{%8,%9},{%0,%1,%2,%3};"
        : "+f"(c[0]), "+f"(c[1]), "+f"(c[2]), "+f"(c[3])
        : "r"(a0), "r"(a1), "r"(a2), "r"(a3), "r"(b0), "r"(b1));
}
// column permutation within each 8-block so logical (c, c+4) sit adjacent:
// 0,1,2,3,4,5,6,7 -> 0,2,4,6,1,3,5,7
__device__ __forceinline__ int permc(int h) {
    return (h & ~7) | ((h & 3) << 1) | ((h >> 2) & 1);
}

// =================================================================
// GEMM: C[4096,1024] = A[4096,1024] @ W[1024,1024], raw mma tf32.
// (unchanged from R7 — validated at ~87us per GEMM)
// =================================================================
#define SA_STRIDE 36
#define SB_STRIDE 136
#define SA_BUF (128 * SA_STRIDE)
#define SB_BUF (32 * SB_STRIDE)

__global__ __launch_bounds__(256) void gemm_tf32_mma(
    const float* __restrict__ A, const float* __restrict__ Wm,
    float* __restrict__ C, int permuted)
{
    extern __shared__ float sm[];
    float* sA = sm;                  // 2 x [128][36]
    float* sB = sm + 2 * SA_BUF;     // 2 x [32][136]

    const int tid  = threadIdx.x;
    const int wid  = tid >> 5;
    const int lane = tid & 31;
    const int gi   = lane >> 2;
    const int ti   = lane & 3;
    const int wm   = wid >> 2;
    const int wn   = wid & 3;
    const int m0   = blockIdx.y * 128;
    const int n0   = blockIdx.x * 128;

    const int arow = tid >> 3;
    const int acol = (tid & 7) << 2;
    const int brow = tid >> 5;
    const int bcol = (tid & 31) << 2;
    const float* Aptr = A + (size_t)(m0 + arow) * GK + acol;
    const float* Bptr = Wm + (size_t)brow * HH + n0 + bcol;

    float acc[4][4][4];
    #pragma unroll
    for (int mi = 0; mi < 4; mi++)
        #pragma unroll
        for (int ni = 0; ni < 4; ni++)
            #pragma unroll
            for (int e = 0; e < 4; e++) acc[mi][ni][e] = 0.0f;

    float4 ra[4], rb[4];

    #pragma unroll
    for (int i = 0; i < 4; i++) {
        ra[i] = *reinterpret_cast<const float4*>(Aptr + (size_t)(32 * i) * GK);
        rb[i] = *reinterpret_cast<const float4*>(Bptr + (size_t)(8 * i) * HH);
    }
    {
        float* sAb = sA;
        float* sBb = sB;
        #pragma unroll
        for (int i = 0; i < 4; i++) {
            float* d = &sAb[(arow + 32 * i) * SA_STRIDE];
            d[permc(acol + 0)] = cvtf(ra[i].x);
            d[permc(acol + 1)] = cvtf(ra[i].y);
            d[permc(acol + 2)] = cvtf(ra[i].z);
            d[permc(acol + 3)] = cvtf(ra[i].w);
            float4 t;
            t.x = cvtf(rb[i].x); t.y = cvtf(rb[i].y);
            t.z = cvtf(rb[i].z); t.w = cvtf(rb[i].w);
            *reinterpret_cast<float4*>(&sBb[(brow + 8 * i) * SB_STRIDE + bcol]) = t;
        }
    }
    __syncthreads();

    int buf = 0;
    const int NKT = GK / 32;
    for (int kt = 0; kt < NKT; kt++) {
        if (kt + 1 < NKT) {
            const int kk = (kt + 1) * 32;
            #pragma unroll
            for (int i = 0; i < 4; i++) {
                ra[i] = *reinterpret_cast<const float4*>(Aptr + kk + (size_t)(32 * i) * GK);
                rb[i] = *reinterpret_cast<const float4*>(Bptr + (size_t)(kk + 8 * i) * HH);
            }
        }

        const float* sAc = sA + buf * SA_BUF;
        const float* sBc = sB + buf * SB_BUF;
        #pragma unroll
        for (int ks = 0; ks < 4; ks++) {
            uint32_t af[4][4];
            #pragma unroll
            for (int mi = 0; mi < 4; mi++) {
                int row = wm * 64 + mi * 16 + gi;
                float2 lo = *reinterpret_cast<const float2*>(&sAc[row * SA_STRIDE + ks * 8 + 2 * ti]);
                float2 hi = *reinterpret_cast<const float2*>(&sAc[(row + 8) * SA_STRIDE + ks * 8 + 2 * ti]);
                af[mi][0] = __float_as_uint(lo.x);
                af[mi][1] = __float_as_uint(hi.x);
                af[mi][2] = __float_as_uint(lo.y);
                af[mi][3] = __float_as_uint(hi.y);
            }
            #pragma unroll
            for (int ni = 0; ni < 4; ni++) {
                int nc = wn * 32 + ni * 8 + gi;
                uint32_t b0 = __float_as_uint(sBc[(ks * 8 + ti) * SB_STRIDE + nc]);
                uint32_t b1 = __float_as_uint(sBc[(ks * 8 + ti + 4) * SB_STRIDE + nc]);
                #pragma unroll
                for (int mi = 0; mi < 4; mi++)
                    mma_tf32_16n8k8(acc[mi][ni], af[mi][0], af[mi][1], af[mi][2], af[mi][3], b0, b1);
            }
        }

        if (kt + 1 < NKT) {
            float* sAb = sA + (buf ^ 1) * SA_BUF;
            float* sBb = sB + (buf ^ 1) * SB_BUF;
            #pragma unroll
            for (int i = 0; i < 4; i++) {
                float* d = &sAb[(arow + 32 * i) * SA_STRIDE];
                d[permc(acol + 0)] = cvtf(ra[i].x);
                d[permc(acol + 1)] = cvtf(ra[i].y);
                d[permc(acol + 2)] = cvtf(ra[i].z);
                d[permc(acol + 3)] = cvtf(ra[i].w);
                float4 t;
                t.x = cvtf(rb[i].x); t.y = cvtf(rb[i].y);
                t.z = cvtf(rb[i].z); t.w = cvtf(rb[i].w);
                *reinterpret_cast<float4*>(&sBb[(brow + 8 * i) * SB_STRIDE + bcol]) = t;
            }
            __syncthreads();
            buf ^= 1;
        }
    }

    #pragma unroll
    for (int mi = 0; mi < 4; mi++) {
        #pragma unroll
        for (int ni = 0; ni < 4; ni++) {
            int r0 = m0 + wm * 64 + mi * 16 + gi;
            int c0 = n0 + wn * 32 + ni * 8 + 2 * ti;
            if (permuted) {
                int b  = r0 >> 11;
                int s  = r0 & (SS - 1);
                int h  = c0 >> 6;
                int hd = c0 & (HD - 1);
                float* p0 = C + (((size_t)(b * NHH + h) * SS + s) << 6) + hd;
                *reinterpret_cast<float2*>(p0) = make_float2(acc[mi][ni][0], acc[mi][ni][1]);
                int r1 = r0 + 8;
                int s1 = r1 & (SS - 1);
                int b1 = r1 >> 11;
                float* p1 = C + (((size_t)(b1 * NHH + h) * SS + s1) << 6) + hd;
                *reinterpret_cast<float2*>(p1) = make_float2(acc[mi][ni][2], acc[mi][ni][3]);
            } else {
                *reinterpret_cast<float2*>(&C[(size_t)r0 * HH + c0]) =
                    make_float2(acc[mi][ni][0], acc[mi][ni][1]);
                *reinterpret_cast<float2*>(&C[(size_t)(r0 + 8) * HH + c0]) =
                    make_float2(acc[mi][ni][2], acc[mi][ni][3]);
            }
        }
    }
}

// =================================================================
// Flash attention v3: 4 warps/CTA, 32 query rows per warp (2 strips),
// K/V fragments amortized over both strips; Q/K/V pre-converted to
// tf32 at smem store; scale folded into Q (exact power of 2).
// =================================================================
__global__ __launch_bounds__(128, 2) void attn_kernel(
    const float* __restrict__ Q, const float* __restrict__ Kg,
    const float* __restrict__ Vg, const int* __restrict__ maskg,
    float* __restrict__ CTX)
{
    extern __shared__ float smbuf[];
    float* sQ = smbuf;                       // [128][68], permuted, tf32*0.125
    float* sK = sQ + 128 * 68;               // [64][68], permuted, tf32
    float* sV = sK + 64 * 68;                // [64 keys][72 hd], tf32
    float* sBias = sV + 64 * 72;             // [64]

    const int tid  = threadIdx.x;
    const int wid  = tid >> 5;    // 0..3
    const int lane = tid & 31;
    const int gi   = lane >> 2;
    const int ti   = lane & 3;
    const int q0   = blockIdx.x * QTILE;
    const int h    = blockIdx.y;
    const int b    = blockIdx.z;
    const size_t off = ((size_t)(b * NHH + h) * SS) << 6;

    // ---- load Q tile (128x64), prescaled + tf32, permuted ----
    #pragma unroll
    for (int i = 0; i < 16; i++) {
        int lin = tid + i * 128;
        int r = lin >> 4;
        int c4 = (lin & 15) << 2;
        float4 v = *reinterpret_cast<const float4*>(&Q[off + ((size_t)(q0 + r) << 6) + c4]);
        sQ[r * 68 + permc(c4 + 0)] = cvtf(v.x * 0.125f);
        sQ[r * 68 + permc(c4 + 1)] = cvtf(v.y * 0.125f);
        sQ[r * 68 + permc(c4 + 2)] = cvtf(v.z * 0.125f);
        sQ[r * 68 + permc(c4 + 3)] = cvtf(v.w * 0.125f);
    }

    // per-thread state: strip0 rows (ar0, ar0+8), strip1 rows (+16, +24)
    float o0[8][4], o1[8][4];
    #pragma unroll
    for (int j = 0; j < 8; j++)
        #pragma unroll
        for (int e = 0; e < 4; e++) { o0[j][e] = 0.0f; o1[j][e] = 0.0f; }
    float m00 = -INFINITY, m01 = -INFINITY, m10 = -INFINITY, m11 = -INFINITY;
    float l00 = 0.0f, l01 = 0.0f, l10 = 0.0f, l11 = 0.0f;

    const int ar0 = wid * 32 + gi;

    for (int kt = 0; kt < SS / KTILE; kt++) {
        const int k0 = kt * KTILE;

        // ---- load K (permuted, tf32) and V (tf32) tiles ----
        #pragma unroll
        for (int i = 0; i < 8; i++) {
            int lin = tid + i * 128;
            int r = lin >> 4;
            int c4 = (lin & 15) << 2;
            float4 vk = *reinterpret_cast<const float4*>(&Kg[off + ((size_t)(k0 + r) << 6) + c4]);
            sK[r * 68 + permc(c4 + 0)] = cvtf(vk.x);
            sK[r * 68 + permc(c4 + 1)] = cvtf(vk.y);
            sK[r * 68 + permc(c4 + 2)] = cvtf(vk.z);
            sK[r * 68 + permc(c4 + 3)] = cvtf(vk.w);
            float4 vv = *reinterpret_cast<const float4*>(&Vg[off + ((size_t)(k0 + r) << 6) + c4]);
            float4 t;
            t.x = cvtf(vv.x); t.y = cvtf(vv.y); t.z = cvtf(vv.z); t.w = cvtf(vv.w);
            *reinterpret_cast<float4*>(&sV[r * 72 + c4]) = t;
        }
        if (tid < KTILE)
            sBias[tid] = (maskg[b * SS + k0 + tid] == 0) ? -1e30f : 0.0f;
        __syncthreads();

        // ---- S = Q @ K^T, both strips, K fragments shared ----
        float s0[8][4], s1[8][4];
        #pragma unroll
        for (int j = 0; j < 8; j++)
            #pragma unroll
            for (int e = 0; e < 4; e++) { s0[j][e] = 0.0f; s1[j][e] = 0.0f; }

        #pragma unroll
        for (int ks = 0; ks < 8; ks++) {
            const float* qp = &sQ[ar0 * 68 + ks * 8 + 2 * ti];
            float2 qa0 = *reinterpret_cast<const float2*>(qp);
            float2 qa1 = *reinterpret_cast<const float2*>(qp + 8 * 68);
            float2 qa2 = *reinterpret_cast<const float2*>(qp + 16 * 68);
            float2 qa3 = *reinterpret_cast<const float2*>(qp + 24 * 68);
            uint32_t a00 = __float_as_uint(qa0.x), a02 = __float_as_uint(qa0.y);
            uint32_t a01 = __float_as_uint(qa1.x), a03 = __float_as_uint(qa1.y);
            uint32_t a10 = __float_as_uint(qa2.x), a12 = __float_as_uint(qa2.y);
            uint32_t a11 = __float_as_uint(qa3.x), a13 = __float_as_uint(qa3.y);
            #pragma unroll
            for (int j = 0; j < 8; j++) {
                float2 kb = *reinterpret_cast<const float2*>(&sK[(j * 8 + gi) * 68 + ks * 8 + 2 * ti]);
                uint32_t b0 = __float_as_uint(kb.x), b1 = __float_as_uint(kb.y);
                mma_tf32_16n8k8(s0[j], a00, a01, a02, a03, b0, b1);
                mma_tf32_16n8k8(s1[j], a10, a11, a12, a13, b0, b1);
            }
        }

        // ---- online softmax, strip 0 ----
        {
            float mloc0 = -INFINITY, mloc1 = -INFINITY;
            #pragma unroll
            for (int j = 0; j < 8; j++) {
                float b0 = sBias[j * 8 + 2 * ti];
                float b1 = sBias[j * 8 + 2 * ti + 1];
                s0[j][0] = fminf(fmaxf(s0[j][0], -10000.0f), 10000.0f) + b0;
                s0[j][1] = fminf(fmaxf(s0[j][1], -10000.0f), 10000.0f) + b1;
                s0[j][2] = fminf(fmaxf(s0[j][2], -10000.0f), 10000.0f) + b0;
                s0[j][3] = fminf(fmaxf(s0[j][3], -10000.0f), 10000.0f) + b1;
                mloc0 = fmaxf(mloc0, fmaxf(s0[j][0], s0[j][1]));
                mloc1 = fmaxf(mloc1, fmaxf(s0[j][2], s0[j][3]));
            }
            mloc0 = fmaxf(mloc0, __shfl_xor_sync(0xffffffffu, mloc0, 1));
            mloc0 = fmaxf(mloc0, __shfl_xor_sync(0xffffffffu, mloc0, 2));
            mloc1 = fmaxf(mloc1, __shfl_xor_sync(0xffffffffu, mloc1, 1));
            mloc1 = fmaxf(mloc1, __shfl_xor_sync(0xffffffffu, mloc1, 2));
            float mn0 = fmaxf(m00, mloc0);
            float mn1 = fmaxf(m01, mloc1);
            float corr0 = __expf(m00 - mn0);
            float corr1 = __expf(m01 - mn1);
            m00 = mn0; m01 = mn1;
            float sum0 = 0.0f, sum1 = 0.0f;
            #pragma unroll
            for (int j = 0; j < 8; j++) {
                s0[j][0] = __expf(s0[j][0] - mn0);
                s0[j][1] = __expf(s0[j][1] - mn0);
                s0[j][2] = __expf(s0[j][2] - mn1);
                s0[j][3] = __expf(s0[j][3] - mn1);
                sum0 += s0[j][0] + s0[j][1];
                sum1 += s0[j][2] + s0[j][3];
            }
            sum0 += __shfl_xor_sync(0xffffffffu, sum0, 1);
            sum0 += __shfl_xor_sync(0xffffffffu, sum0, 2);
            sum1 += __shfl_xor_sync(0xffffffffu, sum1, 1);
            sum1 += __shfl_xor_sync(0xffffffffu, sum1, 2);
            l00 = l00 * corr0 + sum0;
            l01 = l01 * corr1 + sum1;
            #pragma unroll
            for (int j = 0; j < 8; j++) {
                o0[j][0] *= corr0; o0[j][1] *= corr0;
                o0[j][2] *= corr1; o0[j][3] *= corr1;
            }
        }
        // ---- online softmax, strip 1 ----
        {
            float mloc0 = -INFINITY, mloc1 = -INFINITY;
            #pragma unroll
            for (int j = 0; j < 8; j++) {
                float b0 = sBias[j * 8 + 2 * ti];
                float b1 = sBias[j * 8 + 2 * ti + 1];
                s1[j][0] = fminf(fmaxf(s1[j][0], -10000.0f), 10000.0f) + b0;
                s1[j][1] = fminf(fmaxf(s1[j][1], -10000.0f), 10000.0f) + b1;
                s1[j][2] = fminf(fmaxf(s1[j][2], -10000.0f), 10000.0f) + b0;
                s1[j][3] = fminf(fmaxf(s1[j][3], -10000.0f), 10000.0f) + b1;
                mloc0 = fmaxf(mloc0, fmaxf(s1[j][0], s1[j][1]));
                mloc1 = fmaxf(mloc1, fmaxf(s1[j][2], s1[j][3]));
            }
            mloc0 = fmaxf(mloc0, __shfl_xor_sync(0xffffffffu, mloc0, 1));
            mloc0 = fmaxf(mloc0, __shfl_xor_sync(0xffffffffu, mloc0, 2));
            mloc1 = fmaxf(mloc1, __shfl_xor_sync(0xffffffffu, mloc1, 1));
            mloc1 = fmaxf(mloc1, __shfl_xor_sync(0xffffffffu, mloc1, 2));
            float mn0 = fmaxf(m10, mloc0);
            float mn1 = fmaxf(m11, mloc1);
            float corr0 = __expf(m10 - mn0);
            float corr1 = __expf(m11 - mn1);
            m10 = mn0; m11 = mn1;
            float sum0 = 0.0f, sum1 = 0.0f;
            #pragma unroll
            for (int j = 0; j < 8; j++) {
                s1[j][0] = __expf(s1[j][0] - mn0);
                s1[j][1] = __expf(s1[j][1] - mn0);
                s1[j][2] = __expf(s1[j][2] - mn1);
                s1[j][3] = __expf(s1[j][3] - mn1);
                sum0 += s1[j][0] + s1[j][1];
                sum1 += s1[j][2] + s1[j][3];
            }
            sum0 += __shfl_xor_sync(0xffffffffu, sum0, 1);
            sum0 += __shfl_xor_sync(0xffffffffu, sum0, 2);
            sum1 += __shfl_xor_sync(0xffffffffu, sum1, 1);
            sum1 += __shfl_xor_sync(0xffffffffu, sum1, 2);
            l10 = l10 * corr0 + sum0;
            l11 = l11 * corr1 + sum1;
            #pragma unroll
            for (int j = 0; j < 8; j++) {
                o1[j][0] *= corr0; o1[j][1] *= corr0;
                o1[j][2] *= corr1; o1[j][3] *= corr1;
            }
        }

        // ---- O += P @ V, V fragments shared across strips ----
        {
            const int qb   = lane & ~3;
            const int src0 = qb + (ti >> 1);
            const int src1 = src0 + 2;
            const bool odd = (ti & 1);
            #pragma unroll
            for (int kb = 0; kb < 8; kb++) {
                float v00 = __shfl_sync(0xffffffffu, s0[kb][0], src0);
                float v01 = __shfl_sync(0xffffffffu, s0[kb][1], src0);
                float v20 = __shfl_sync(0xffffffffu, s0[kb][0], src1);
                float v21 = __shfl_sync(0xffffffffu, s0[kb][1], src1);
                float v10 = __shfl_sync(0xffffffffu, s0[kb][2], src0);
                float v11 = __shfl_sync(0xffffffffu, s0[kb][3], src0);
                float v30 = __shfl_sync(0xffffffffu, s0[kb][2], src1);
                float v31 = __shfl_sync(0xffffffffu, s0[kb][3], src1);
                uint32_t a0 = f2tf32(odd ? v01 : v00);
                uint32_t a1 = f2tf32(odd ? v11 : v10);
                uint32_t a2 = f2tf32(odd ? v21 : v20);
                uint32_t a3 = f2tf32(odd ? v31 : v30);
                float w00 = __shfl_sync(0xffffffffu, s1[kb][0], src0);
                float w01 = __shfl_sync(0xffffffffu, s1[kb][1], src0);
                float w20 = __shfl_sync(0xffffffffu, s1[kb][0], src1);
                float w21 = __shfl_sync(0xffffffffu, s1[kb][1], src1);
                float w10 = __shfl_sync(0xffffffffu, s1[kb][2], src0);
                float w11 = __shfl_sync(0xffffffffu, s1[kb][3], src0);
                float w30 = __shfl_sync(0xffffffffu, s1[kb][2], src1);
                float w31 = __shfl_sync(0xffffffffu, s1[kb][3], src1);
                uint32_t c0 = f2tf32(odd ? w01 : w00);
                uint32_t c1 = f2tf32(odd ? w11 : w10);
                uint32_t c2 = f2tf32(odd ? w21 : w20);
                uint32_t c3 = f2tf32(odd ? w31 : w30);
                #pragma unroll
                for (int j = 0; j < 8; j++) {
                    uint32_t b0 = __float_as_uint(sV[(kb * 8 + ti) * 72 + j * 8 + gi]);
                    uint32_t b1 = __float_as_uint(sV[(kb * 8 + ti + 4) * 72 + j * 8 + gi]);
                    mma_tf32_16n8k8(o0[j], a0, a1, a2, a3, b0, b1);
                    mma_tf32_16n8k8(o1[j], c0, c1, c2, c3, b0, b1);
                }
            }
        }
        __syncthreads();
    }

    // ---- normalize and write context [B, S, H] ----
    float i00 = 1.0f / l00, i01 = 1.0f / l01;
    float i10 = 1.0f / l10, i11 = 1.0f / l11;
    int row0 = q0 + wid * 32 + gi;
    #pragma unroll
    for (int j = 0; j < 8; j++) {
        int c = h * HD + j * 8 + 2 * ti;
        *reinterpret_cast<float2*>(&CTX[(size_t)(b * SS + row0) * HH + c]) =
            make_float2(o0[j][0] * i00, o0[j][1] * i00);
        *reinterpret_cast<float2*>(&CTX[(size_t)(b * SS + row0 + 8) * HH + c]) =
            make_float2(o0[j][2] * i01, o0[j][3] * i01);
        *reinterpret_cast<float2*>(&CTX[(size_t)(b * SS + row0 + 16) * HH + c]) =
            make_float2(o1[j][0] * i10, o1[j][1] * i10);
        *reinterpret_cast<float2*>(&CTX[(size_t)(b * SS + row0 + 24) * HH + c]) =
            make_float2(o1[j][2] * i11, o1[j][3] * i11);
    }
}

// =================================================================
extern "C" void kernel_launch(void* const* d_in, const int* in_sizes, int n_in,
                              void* d_out, int out_size)
{
    const float* X    = (const float*)d_in[0];
    const int*   mask = (const int*)d_in[1];
    const float* WQ   = (const float*)d_in[2];
    const float* WK   = (const float*)d_in[3];
    const float* WV   = (const float*)d_in[4];
    const float* WO   = (const float*)d_in[5];
    float* out = (float*)d_out;

    float *qb, *kb, *vb, *cb;
    cudaGetSymbolAddress((void**)&qb, g_Q);
    cudaGetSymbolAddress((void**)&kb, g_K);
    cudaGetSymbolAddress((void**)&vb, g_V);
    cudaGetSymbolAddress((void**)&cb, g_CTX);

    size_t gsmem = (size_t)(2 * SA_BUF + 2 * SB_BUF) * sizeof(float);  // ~71.7KB
    cudaFuncSetAttribute(gemm_tf32_mma, cudaFuncAttributeMaxDynamicSharedMemorySize, (int)gsmem);

    dim3 gg(HH / 128, MROWS / 128);   // (8, 32)
    gemm_tf32_mma<<<gg, 256, gsmem>>>(X, WQ, qb, 1);
    gemm_tf32_mma<<<gg, 256, gsmem>>>(X, WK, kb, 1);
    gemm_tf32_mma<<<gg, 256, gsmem>>>(X, WV, vb, 1);

    size_t smem = (size_t)(128 * 68 + 64 * 68 + 64 * 72 + 64) * sizeof(float);
    cudaFuncSetAttribute(attn_kernel, cudaFuncAttributeMaxDynamicSharedMemorySize, (int)smem);
    attn_kernel<<<dim3(SS / QTILE, NHH, BB), 128, smem>>>(qb, kb, vb, mask, cb);

    gemm_tf32_mma<<<gg, 256, gsmem>>>(cb, WO, out, 0);
}

// round 10
// speedup vs baseline: 2.6582x; 1.2292x over previous
#include <cuda_runtime.h>
#include <cuda_bf16.h>
#include <math.h>
#include <stdint.h>

#define BB  2
#define SS  2048
#define HH  1024
#define NHH 16
#define HD  64
#define MROWS (BB*SS)      // 4096
#define GK  1024

#define QTILE 128
#define KTILE 64

// ---------------- scratch (no allocations allowed) ----------------
__device__ float g_Q[(size_t)BB*SS*HH];
__device__ float g_K[(size_t)BB*SS*HH];
__device__ float g_V[(size_t)BB*SS*HH];
__device__ float g_CTX[(size_t)BB*SS*HH];
__device__ float g_Xc[(size_t)MROWS*HH];       // X pre-rounded to tf32
__device__ float g_Wc0[(size_t)GK*HH];         // W_Q rounded
__device__ float g_Wc1[(size_t)GK*HH];         // W_K
__device__ float g_Wc2[(size_t)GK*HH];         // W_V
__device__ float g_Wc3[(size_t)GK*HH];         // W_O

// =================================================================
// helpers
// =================================================================
__device__ __forceinline__ uint32_t f2tf32(float x) {
    uint32_t u;
    asm("cvt.rna.tf32.f32 %0, %1;" : "=r"(u) : "f"(x));
    return u;
}
__device__ __forceinline__ float cvtf(float x) {
    return __uint_as_float(f2tf32(x));
}
__device__ __forceinline__ void mma_tf32_16n8k8(float* c,
    uint32_t a0, uint32_t a1, uint32_t a2, uint32_t a3,
    uint32_t b0, uint32_t b1)
{
    asm volatile("mma.sync.aligned.m16n8k8.row.col.f32.tf32.tf32.f32 "
        "{%0,%1,%2,%3},{%4,%5,%6,%7},{%8,%9},{%0,%1,%2,%3};"
        : "+f"(c[0]), "+f"(c[1]), "+f"(c[2]), "+f"(c[3])
        : "r"(a0), "r"(a1), "r"(a2), "r"(a3), "r"(b0), "r"(b1));
}
// ldmatrix x4 on fp32 data (b16 view): gives the tf32 m16k8 A-fragment.
__device__ __forceinline__ void ldsm4(uint32_t& r0, uint32_t& r1,
                                      uint32_t& r2, uint32_t& r3, uint32_t a) {
    asm volatile("ldmatrix.sync.aligned.m8n8.x4.shared.b16 {%0,%1,%2,%3}, [%4];"
        : "=r"(r0), "=r"(r1), "=r"(r2), "=r"(r3) : "r"(a));
}
__device__ __forceinline__ int permc(int h) {
    return (h & ~7) | ((h & 3) << 1) | ((h >> 2) & 1);
}

// =================================================================
// elementwise tf32-round pre-pass
// =================================================================
__global__ void cvt_tf32_kernel(const float* __restrict__ src,
                                float* __restrict__ dst, int n4)
{
    int i = blockIdx.x * blockDim.x + threadIdx.x;
    if (i < n4) {
        float4 v = reinterpret_cast<const float4*>(src)[i];
        v.x = cvtf(v.x); v.y = cvtf(v.y); v.z = cvtf(v.z); v.w = cvtf(v.w);
        reinterpret_cast<float4*>(dst)[i] = v;
    }
}

// =================================================================
// GEMM: C[4096,1024] = A @ W, inputs pre-rounded to tf32.
// 128x128 CTA tile, 128 threads (4 warps, 64x64 warp tiles),
// 3-stage cp.async pipeline, ldmatrix A-fragments.
// =================================================================
#define STAGES 3
#define SA_ST 36
#define SB_ST 136
#define SA_TILE (128 * SA_ST)   // words per stage
#define SB_TILE (32 * SB_ST)

__global__ __launch_bounds__(128) void gemm_tf32_cp(
    const float* __restrict__ A, const float* __restrict__ Wm,
    float* __restrict__ C, int permuted)
{
    extern __shared__ float sm[];
    float* sB = sm + STAGES * SA_TILE;

    const int tid  = threadIdx.x;
    const int wid  = tid >> 5;
    const int lane = tid & 31;
    const int gi   = lane >> 2;
    const int ti   = lane & 3;
    const int wm   = wid >> 1;   // 0..1
    const int wn   = wid & 1;    // 0..1
    const int m0   = blockIdx.y * 128;
    const int n0   = blockIdx.x * 128;

    const float* Abase = A + (size_t)m0 * GK;
    const float* Bbase = Wm + n0;
    const uint32_t smbase = (uint32_t)__cvta_generic_to_shared(sm);

    // copy chunk indices (16B granules)
    const int acr = tid >> 3, acs = (tid & 7) << 2;         // A: +16 rows/iter
    const int bcr = tid >> 5, bcs = (tid & 31) << 2;        // B: +4 rows/iter

    #define ISSUE_TILE(kt, stg)                                              \
    {                                                                        \
        uint32_t sa_ = smbase + (uint32_t)(stg) * SA_TILE * 4;               \
        uint32_t sb_ = smbase + (uint32_t)(STAGES * SA_TILE +                \
                                           (stg) * SB_TILE) * 4;             \
        const float* ga_ = Abase + (kt) * 32;                                \
        const float* gb_ = Bbase + (size_t)(kt) * 32 * HH;                   \
        _Pragma("unroll")                                                    \
        for (int i_ = 0; i_ < 8; i_++) {                                     \
            int r_ = acr + i_ * 16;                                          \
            asm volatile("cp.async.cg.shared.global [%0],[%1],16;" ::        \
                "r"(sa_ + (uint32_t)(r_ * SA_ST + acs) * 4),                 \
                "l"(ga_ + (size_t)r_ * GK + acs));                           \
        }                                                                    \
        _Pragma("unroll")                                                    \
        for (int i_ = 0; i_ < 8; i_++) {                                     \
            int r_ = bcr + i_ * 4;                                           \
            asm volatile("cp.async.cg.shared.global [%0],[%1],16;" ::        \
                "r"(sb_ + (uint32_t)(r_ * SB_ST + bcs) * 4),                 \
                "l"(gb_ + (size_t)r_ * HH + bcs));                           \
        }                                                                    \
        asm volatile("cp.async.commit_group;");                              \
    }

    float acc[4][8][4];
    #pragma unroll
    for (int mi = 0; mi < 4; mi++)
        #pragma unroll
        for (int ni = 0; ni < 8; ni++)
            #pragma unroll
            for (int e = 0; e < 4; e++) acc[mi][ni][e] = 0.0f;

    ISSUE_TILE(0, 0);
    ISSUE_TILE(1, 1);

    // per-lane ldmatrix addressing: lanes 0-15 -> rows (lane&15), cols +0;
    // lanes 16-31 -> rows (lane&15), cols +4 (16B offset)
    const int      lrow   = wm * 64 + (lane & 15);
    const uint32_t lcol16 = (lane & 16) ? 16u : 0u;

    const int NKT = GK / 32;
    for (int kt = 0; kt < NKT; kt++) {
        asm volatile("cp.async.wait_group 1;");
        __syncthreads();   // all threads' copies of tile kt visible

        const int stg = kt % STAGES;
        const uint32_t saU = smbase + (uint32_t)stg * SA_TILE * 4;
        const float* sBc = sB + stg * SB_TILE;

        #pragma unroll
        for (int ks = 0; ks < 4; ks++) {
            uint32_t af[4][4];
            #pragma unroll
            for (int mi = 0; mi < 4; mi++) {
                uint32_t addr = saU + (uint32_t)(((lrow + mi * 16) * SA_ST + ks * 8) * 4) + lcol16;
                ldsm4(af[mi][0], af[mi][1], af[mi][2], af[mi][3], addr);
            }
            #pragma unroll
            for (int ni = 0; ni < 8; ni++) {
                int nc = wn * 64 + ni * 8 + gi;
                uint32_t b0 = __float_as_uint(sBc[(ks * 8 + ti) * SB_ST + nc]);
                uint32_t b1 = __float_as_uint(sBc[(ks * 8 + ti + 4) * SB_ST + nc]);
                #pragma unroll
                for (int mi = 0; mi < 4; mi++)
                    mma_tf32_16n8k8(acc[mi][ni], af[mi][0], af[mi][1], af[mi][2], af[mi][3], b0, b1);
            }
        }
        // safe: every thread has passed this iter's barrier, so no one still
        // reads stage (kt+2)%3 (== stage kt-1, finished before the barrier)
        if (kt + 2 < NKT) ISSUE_TILE(kt + 2, (kt + 2) % STAGES);
    }

    // ---- epilogue ----
    #pragma unroll
    for (int mi = 0; mi < 4; mi++) {
        #pragma unroll
        for (int ni = 0; ni < 8; ni++) {
            int r0 = m0 + wm * 64 + mi * 16 + gi;
            int c0 = n0 + wn * 64 + ni * 8 + 2 * ti;
            if (permuted) {
                int b  = r0 >> 11;
                int s  = r0 & (SS - 1);
                int h  = c0 >> 6;
                int hd = c0 & (HD - 1);
                float* p0 = C + (((size_t)(b * NHH + h) * SS + s) << 6) + hd;
                *reinterpret_cast<float2*>(p0) = make_float2(acc[mi][ni][0], acc[mi][ni][1]);
                int r1 = r0 + 8;
                int s1 = r1 & (SS - 1);
                int b1 = r1 >> 11;
                float* p1 = C + (((size_t)(b1 * NHH + h) * SS + s1) << 6) + hd;
                *reinterpret_cast<float2*>(p1) = make_float2(acc[mi][ni][2], acc[mi][ni][3]);
            } else {
                *reinterpret_cast<float2*>(&C[(size_t)r0 * HH + c0]) =
                    make_float2(acc[mi][ni][0], acc[mi][ni][1]);
                *reinterpret_cast<float2*>(&C[(size_t)(r0 + 8) * HH + c0]) =
                    make_float2(acc[mi][ni][2], acc[mi][ni][3]);
            }
        }
    }
    #undef ISSUE_TILE
}

// =================================================================
// Flash attention v3 (R9, validated 324us): 4 warps, 32 q-rows/warp.
// Only change: CTX written tf32-rounded so O-proj GEMM consumes it
// directly (identical numerics to rounding at GEMM load).
// =================================================================
__global__ __launch_bounds__(128, 2) void attn_kernel(
    const float* __restrict__ Q, const float* __restrict__ Kg,
    const float* __restrict__ Vg, const int* __restrict__ maskg,
    float* __restrict__ CTX)
{
    extern __shared__ float smbuf[];
    float* sQ = smbuf;                       // [128][68], permuted, tf32*0.125
    float* sK = sQ + 128 * 68;               // [64][68], permuted, tf32
    float* sV = sK + 64 * 68;                // [64 keys][72 hd], tf32
    float* sBias = sV + 64 * 72;             // [64]

    const int tid  = threadIdx.x;
    const int wid  = tid >> 5;
    const int lane = tid & 31;
    const int gi   = lane >> 2;
    const int ti   = lane & 3;
    const int q0   = blockIdx.x * QTILE;
    const int h    = blockIdx.y;
    const int b    = blockIdx.z;
    const size_t off = ((size_t)(b * NHH + h) * SS) << 6;

    #pragma unroll
    for (int i = 0; i < 16; i++) {
        int lin = tid + i * 128;
        int r = lin >> 4;
        int c4 = (lin & 15) << 2;
        float4 v = *reinterpret_cast<const float4*>(&Q[off + ((size_t)(q0 + r) << 6) + c4]);
        sQ[r * 68 + permc(c4 + 0)] = cvtf(v.x * 0.125f);
        sQ[r * 68 + permc(c4 + 1)] = cvtf(v.y * 0.125f);
        sQ[r * 68 + permc(c4 + 2)] = cvtf(v.z * 0.125f);
        sQ[r * 68 + permc(c4 + 3)] = cvtf(v.w * 0.125f);
    }

    float o0[8][4], o1[8][4];
    #pragma unroll
    for (int j = 0; j < 8; j++)
        #pragma unroll
        for (int e = 0; e < 4; e++) { o0[j][e] = 0.0f; o1[j][e] = 0.0f; }
    float m00 = -INFINITY, m01 = -INFINITY, m10 = -INFINITY, m11 = -INFINITY;
    float l00 = 0.0f, l01 = 0.0f, l10 = 0.0f, l11 = 0.0f;

    const int ar0 = wid * 32 + gi;

    for (int kt = 0; kt < SS / KTILE; kt++) {
        const int k0 = kt * KTILE;

        #pragma unroll
        for (int i = 0; i < 8; i++) {
            int lin = tid + i * 128;
            int r = lin >> 4;
            int c4 = (lin & 15) << 2;
            float4 vk = *reinterpret_cast<const float4*>(&Kg[off + ((size_t)(k0 + r) << 6) + c4]);
            sK[r * 68 + permc(c4 + 0)] = cvtf(vk.x);
            sK[r * 68 + permc(c4 + 1)] = cvtf(vk.y);
            sK[r * 68 + permc(c4 + 2)] = cvtf(vk.z);
            sK[r * 68 + permc(c4 + 3)] = cvtf(vk.w);
            float4 vv = *reinterpret_cast<const float4*>(&Vg[off + ((size_t)(k0 + r) << 6) + c4]);
            float4 t;
            t.x = cvtf(vv.x); t.y = cvtf(vv.y); t.z = cvtf(vv.z); t.w = cvtf(vv.w);
            *reinterpret_cast<float4*>(&sV[r * 72 + c4]) = t;
        }
        if (tid < KTILE)
            sBias[tid] = (maskg[b * SS + k0 + tid] == 0) ? -1e30f : 0.0f;
        __syncthreads();

        float s0[8][4], s1[8][4];
        #pragma unroll
        for (int j = 0; j < 8; j++)
            #pragma unroll
            for (int e = 0; e < 4; e++) { s0[j][e] = 0.0f; s1[j][e] = 0.0f; }

        #pragma unroll
        for (int ks = 0; ks < 8; ks++) {
            const float* qp = &sQ[ar0 * 68 + ks * 8 + 2 * ti];
            float2 qa0 = *reinterpret_cast<const float2*>(qp);
            float2 qa1 = *reinterpret_cast<const float2*>(qp + 8 * 68);
            float2 qa2 = *reinterpret_cast<const float2*>(qp + 16 * 68);
            float2 qa3 = *reinterpret_cast<const float2*>(qp + 24 * 68);
            uint32_t a00 = __float_as_uint(qa0.x), a02 = __float_as_uint(qa0.y);
            uint32_t a01 = __float_as_uint(qa1.x), a03 = __float_as_uint(qa1.y);
            uint32_t a10 = __float_as_uint(qa2.x), a12 = __float_as_uint(qa2.y);
            uint32_t a11 = __float_as_uint(qa3.x), a13 = __float_as_uint(qa3.y);
            #pragma unroll
            for (int j = 0; j < 8; j++) {
                float2 kb = *reinterpret_cast<const float2*>(&sK[(j * 8 + gi) * 68 + ks * 8 + 2 * ti]);
                uint32_t b0 = __float_as_uint(kb.x), b1 = __float_as_uint(kb.y);
                mma_tf32_16n8k8(s0[j], a00, a01, a02, a03, b0, b1);
                mma_tf32_16n8k8(s1[j], a10, a11, a12, a13, b0, b1);
            }
        }

        {
            float mloc0 = -INFINITY, mloc1 = -INFINITY;
            #pragma unroll
            for (int j = 0; j < 8; j++) {
                float b0 = sBias[j * 8 + 2 * ti];
                float b1 = sBias[j * 8 + 2 * ti + 1];
                s0[j][0] = fminf(fmaxf(s0[j][0], -10000.0f), 10000.0f) + b0;
                s0[j][1] = fminf(fmaxf(s0[j][1], -10000.0f), 10000.0f) + b1;
                s0[j][2] = fminf(fmaxf(s0[j][2], -10000.0f), 10000.0f) + b0;
                s0[j][3] = fminf(fmaxf(s0[j][3], -10000.0f), 10000.0f) + b1;
                mloc0 = fmaxf(mloc0, fmaxf(s0[j][0], s0[j][1]));
                mloc1 = fmaxf(mloc1, fmaxf(s0[j][2], s0[j][3]));
            }
            mloc0 = fmaxf(mloc0, __shfl_xor_sync(0xffffffffu, mloc0, 1));
            mloc0 = fmaxf(mloc0, __shfl_xor_sync(0xffffffffu, mloc0, 2));
            mloc1 = fmaxf(mloc1, __shfl_xor_sync(0xffffffffu, mloc1, 1));
            mloc1 = fmaxf(mloc1, __shfl_xor_sync(0xffffffffu, mloc1, 2));
            float mn0 = fmaxf(m00, mloc0);
            float mn1 = fmaxf(m01, mloc1);
            float corr0 = __expf(m00 - mn0);
            float corr1 = __expf(m01 - mn1);
            m00 = mn0; m01 = mn1;
            float sum0 = 0.0f, sum1 = 0.0f;
            #pragma unroll
            for (int j = 0; j < 8; j++) {
                s0[j][0] = __expf(s0[j][0] - mn0);
                s0[j][1] = __expf(s0[j][1] - mn0);
                s0[j][2] = __expf(s0[j][2] - mn1);
                s0[j][3] = __expf(s0[j][3] - mn1);
                sum0 += s0[j][0] + s0[j][1];
                sum1 += s0[j][2] + s0[j][3];
            }
            sum0 += __shfl_xor_sync(0xffffffffu, sum0, 1);
            sum0 += __shfl_xor_sync(0xffffffffu, sum0, 2);
            sum1 += __shfl_xor_sync(0xffffffffu, sum1, 1);
            sum1 += __shfl_xor_sync(0xffffffffu, sum1, 2);
            l00 = l00 * corr0 + sum0;
            l01 = l01 * corr1 + sum1;
            #pragma unroll
            for (int j = 0; j < 8; j++) {
                o0[j][0] *= corr0; o0[j][1] *= corr0;
                o0[j][2] *= corr1; o0[j][3] *= corr1;
            }
        }
        {
            float mloc0 = -INFINITY, mloc1 = -INFINITY;
            #pragma unroll
            for (int j = 0; j < 8; j++) {
                float b0 = sBias[j * 8 + 2 * ti];
                float b1 = sBias[j * 8 + 2 * ti + 1];
                s1[j][0] = fminf(fmaxf(s1[j][0], -10000.0f), 10000.0f) + b0;
                s1[j][1] = fminf(fmaxf(s1[j][1], -10000.0f), 10000.0f) + b1;
                s1[j][2] = fminf(fmaxf(s1[j][2], -10000.0f), 10000.0f) + b0;
                s1[j][3] = fminf(fmaxf(s1[j][3], -10000.0f), 10000.0f) + b1;
                mloc0 = fmaxf(mloc0, fmaxf(s1[j][0], s1[j][1]));
                mloc1 = fmaxf(mloc1, fmaxf(s1[j][2], s1[j][3]));
            }
            mloc0 = fmaxf(mloc0, __shfl_xor_sync(0xffffffffu, mloc0, 1));
            mloc0 = fmaxf(mloc0, __shfl_xor_sync(0xffffffffu, mloc0, 2));
            mloc1 = fmaxf(mloc1, __shfl_xor_sync(0xffffffffu, mloc1, 1));
            mloc1 = fmaxf(mloc1, __shfl_xor_sync(0xffffffffu, mloc1, 2));
            float mn0 = fmaxf(m10, mloc0);
            float mn1 = fmaxf(m11, mloc1);
            float corr0 = __expf(m10 - mn0);
            float corr1 = __expf(m11 - mn1);
            m10 = mn0; m11 = mn1;
            float sum0 = 0.0f, sum1 = 0.0f;
            #pragma unroll
            for (int j = 0; j < 8; j++) {
                s1[j][0] = __expf(s1[j][0] - mn0);
                s1[j][1] = __expf(s1[j][1] - mn0);
                s1[j][2] = __expf(s1[j][2] - mn1);
                s1[j][3] = __expf(s1[j][3] - mn1);
                sum0 += s1[j][0] + s1[j][1];
                sum1 += s1[j][2] + s1[j][3];
            }
            sum0 += __shfl_xor_sync(0xffffffffu, sum0, 1);
            sum0 += __shfl_xor_sync(0xffffffffu, sum0, 2);
            sum1 += __shfl_xor_sync(0xffffffffu, sum1, 1);
            sum1 += __shfl_xor_sync(0xffffffffu, sum1, 2);
            l10 = l10 * corr0 + sum0;
            l11 = l11 * corr1 + sum1;
            #pragma unroll
            for (int j = 0; j < 8; j++) {
                o1[j][0] *= corr0; o1[j][1] *= corr0;
                o1[j][2] *= corr1; o1[j][3] *= corr1;
            }
        }

        {
            const int qb   = lane & ~3;
            const int src0 = qb + (ti >> 1);
            const int src1 = src0 + 2;
            const bool odd = (ti & 1);
            #pragma unroll
            for (int kb = 0; kb < 8; kb++) {
                float v00 = __shfl_sync(0xffffffffu, s0[kb][0], src0);
                float v01 = __shfl_sync(0xffffffffu, s0[kb][1], src0);
                float v20 = __shfl_sync(0xffffffffu, s0[kb][0], src1);
                float v21 = __shfl_sync(0xffffffffu, s0[kb][1], src1);
                float v10 = __shfl_sync(0xffffffffu, s0[kb][2], src0);
                float v11 = __shfl_sync(0xffffffffu, s0[kb][3], src0);
                float v30 = __shfl_sync(0xffffffffu, s0[kb][2], src1);
                float v31 = __shfl_sync(0xffffffffu, s0[kb][3], src1);
                uint32_t a0 = f2tf32(odd ? v01 : v00);
                uint32_t a1 = f2tf32(odd ? v11 : v10);
                uint32_t a2 = f2tf32(odd ? v21 : v20);
                uint32_t a3 = f2tf32(odd ? v31 : v30);
                float w00 = __shfl_sync(0xffffffffu, s1[kb][0], src0);
                float w01 = __shfl_sync(0xffffffffu, s1[kb][1], src0);
                float w20 = __shfl_sync(0xffffffffu, s1[kb][0], src1);
                float w21 = __shfl_sync(0xffffffffu, s1[kb][1], src1);
                float w10 = __shfl_sync(0xffffffffu, s1[kb][2], src0);
                float w11 = __shfl_sync(0xffffffffu, s1[kb][3], src0);
                float w30 = __shfl_sync(0xffffffffu, s1[kb][2], src1);
                float w31 = __shfl_sync(0xffffffffu, s1[kb][3], src1);
                uint32_t c0 = f2tf32(odd ? w01 : w00);
                uint32_t c1 = f2tf32(odd ? w11 : w10);
                uint32_t c2 = f2tf32(odd ? w21 : w20);
                uint32_t c3 = f2tf32(odd ? w31 : w30);
                #pragma unroll
                for (int j = 0; j < 8; j++) {
                    uint32_t b0 = __float_as_uint(sV[(kb * 8 + ti) * 72 + j * 8 + gi]);
                    uint32_t b1 = __float_as_uint(sV[(kb * 8 + ti + 4) * 72 + j * 8 + gi]);
                    mma_tf32_16n8k8(o0[j], a0, a1, a2, a3, b0, b1);
                    mma_tf32_16n8k8(o1[j], c0, c1, c2, c3, b0, b1);
                }
            }
        }
        __syncthreads();
    }

    // ---- normalize, round to tf32, write context [B, S, H] ----
    float i00 = 1.0f / l00, i01 = 1.0f / l01;
    float i10 = 1.0f / l10, i11 = 1.0f / l11;
    int row0 = q0 + wid * 32 + gi;
    #pragma unroll
    for (int j = 0; j < 8; j++) {
        int c = h * HD + j * 8 + 2 * ti;
        *reinterpret_cast<float2*>(&CTX[(size_t)(b * SS + row0) * HH + c]) =
            make_float2(cvtf(o0[j][0] * i00), cvtf(o0[j][1] * i00));
        *reinterpret_cast<float2*>(&CTX[(size_t)(b * SS + row0 + 8) * HH + c]) =
            make_float2(cvtf(o0[j][2] * i01), cvtf(o0[j][3] * i01));
        *reinterpret_cast<float2*>(&CTX[(size_t)(b * SS + row0 + 16) * HH + c]) =
            make_float2(cvtf(o1[j][0] * i10), cvtf(o1[j][1] * i10));
        *reinterpret_cast<float2*>(&CTX[(size_t)(b * SS + row0 + 24) * HH + c]) =
            make_float2(cvtf(o1[j][2] * i11), cvtf(o1[j][3] * i11));
    }
}

// =================================================================
extern "C" void kernel_launch(void* const* d_in, const int* in_sizes, int n_in,
                              void* d_out, int out_size)
{
    const float* X    = (const float*)d_in[0];
    const int*   mask = (const int*)d_in[1];
    const float* WQ   = (const float*)d_in[2];
    const float* WK   = (const float*)d_in[3];
    const float* WV   = (const float*)d_in[4];
    const float* WO   = (const float*)d_in[5];
    float* out = (float*)d_out;

    float *qb, *kb, *vb, *cb, *xc, *w0, *w1, *w2, *w3;
    cudaGetSymbolAddress((void**)&qb, g_Q);
    cudaGetSymbolAddress((void**)&kb, g_K);
    cudaGetSymbolAddress((void**)&vb, g_V);
    cudaGetSymbolAddress((void**)&cb, g_CTX);
    cudaGetSymbolAddress((void**)&xc, g_Xc);
    cudaGetSymbolAddress((void**)&w0, g_Wc0);
    cudaGetSymbolAddress((void**)&w1, g_Wc1);
    cudaGetSymbolAddress((void**)&w2, g_Wc2);
    cudaGetSymbolAddress((void**)&w3, g_Wc3);

    // pre-round inputs to tf32 (X reused by 3 GEMMs)
    const int nx4 = MROWS * HH / 4;   // 1M
    const int nw4 = GK * HH / 4;      // 256K
    cvt_tf32_kernel<<<(nx4 + 255) / 256, 256>>>(X, xc, nx4);
    cvt_tf32_kernel<<<(nw4 + 255) / 256, 256>>>(WQ, w0, nw4);
    cvt_tf32_kernel<<<(nw4 + 255) / 256, 256>>>(WK, w1, nw4);
    cvt_tf32_kernel<<<(nw4 + 255) / 256, 256>>>(WV, w2, nw4);
    cvt_tf32_kernel<<<(nw4 + 255) / 256, 256>>>(WO, w3, nw4);

    size_t gsmem = (size_t)STAGES * (SA_TILE + SB_TILE) * sizeof(float);  // 107520
    cudaFuncSetAttribute(gemm_tf32_cp, cudaFuncAttributeMaxDynamicSharedMemorySize, (int)gsmem);

    dim3 gg(HH / 128, MROWS / 128);   // (8, 32)
    gemm_tf32_cp<<<gg, 128, gsmem>>>(xc, w0, qb, 1);
    gemm_tf32_cp<<<gg, 128, gsmem>>>(xc, w1, kb, 1);
    gemm_tf32_cp<<<gg, 128, gsmem>>>(xc, w2, vb, 1);

    size_t smem = (size_t)(128 * 68 + 64 * 68 + 64 * 72 + 64) * sizeof(float);
    cudaFuncSetAttribute(attn_kernel, cudaFuncAttributeMaxDynamicSharedMemorySize, (int)smem);
    attn_kernel<<<dim3(SS / QTILE, NHH, BB), 128, smem>>>(qb, kb, vb, mask, cb);

    gemm_tf32_cp<<<gg, 128, gsmem>>>(cb, w3, out, 0);
}